// round 5
// baseline (speedup 1.0000x reference)
#include <cuda_runtime.h>
#include <math.h>

static constexpr int kHeads = 16;
static constexpr int kD     = 64;
static constexpr int kB     = 2;
static constexpr int kN     = 2048;
static constexpr int kDim   = 1024;
static constexpr int kRows  = kB * kN;          // 4096
static constexpr int kQkvN  = 3 * kHeads * kD;  // 3072
static constexpr int kKV    = kN + 4;           // 2052

// ---------------- scratch (device globals; no allocation) ----------------
__device__ float g_wn_qkv[(size_t)kQkvN * kDim];
__device__ float g_wn_out[(size_t)kDim * kDim];
__device__ float g_qkv[(size_t)kRows * kQkvN];
__device__ float g_attn[(size_t)kRows * kDim];

// ---------------- weight row l2-norm: wn = w / (max(||row||,eps)*sqrt(1024)) ----------------
__global__ __launch_bounds__(256) void norm_rows_kernel(const float* __restrict__ w, int which) {
  float* wn = which ? g_wn_out : g_wn_qkv;
  const int row = blockIdx.x;
  const int t = threadIdx.x;  // 256 threads, 1024 cols -> 1 float4 each
  float4 v = ((const float4*)(w + (size_t)row * kDim))[t];
  float ss = v.x * v.x + v.y * v.y + v.z * v.z + v.w * v.w;
#pragma unroll
  for (int off = 16; off; off >>= 1) ss += __shfl_xor_sync(0xffffffffu, ss, off);
  __shared__ float red[8];
  if ((t & 31) == 0) red[t >> 5] = ss;
  __syncthreads();
  float tot = red[0] + red[1] + red[2] + red[3] + red[4] + red[5] + red[6] + red[7];
  float sc = 1.0f / (fmaxf(sqrtf(tot), 1e-4f) * 32.0f);  // 32 = sqrt(1024)
  ((float4*)(wn + (size_t)row * kDim))[t] = make_float4(v.x * sc, v.y * sc, v.z * sc, v.w * sc);
}

// ---------------- 128x128x8 SGEMM core: C[m,n] = sum_k A[m,k]*B[n,k] ----------------
template <int NCOLS, bool FUSE>
__device__ __forceinline__ void sgemm_core(const float* __restrict__ A,
                                           const float* __restrict__ Bw,
                                           float* __restrict__ C,
                                           const float* __restrict__ resid) {
  __shared__ float As[8][128];
  __shared__ float Bs[8][128];
  const int t  = threadIdx.x;          // 256
  const int m0 = blockIdx.y * 128;
  const int n0 = blockIdx.x * 128;
  const int tx = t & 15, ty = t >> 4;
  const int lRow = t >> 1;             // 0..127
  const int lK   = (t & 1) * 4;        // 0 or 4
  const float* Ap = A  + (size_t)(m0 + lRow) * kDim + lK;
  const float* Bp = Bw + (size_t)(n0 + lRow) * kDim + lK;

  float acc[8][8];
#pragma unroll
  for (int i = 0; i < 8; i++)
#pragma unroll
    for (int j = 0; j < 8; j++) acc[i][j] = 0.f;

  for (int k0 = 0; k0 < kDim; k0 += 8) {
    float4 av = *(const float4*)(Ap + k0);
    float4 bv = *(const float4*)(Bp + k0);
    As[lK + 0][lRow] = av.x; As[lK + 1][lRow] = av.y;
    As[lK + 2][lRow] = av.z; As[lK + 3][lRow] = av.w;
    Bs[lK + 0][lRow] = bv.x; Bs[lK + 1][lRow] = bv.y;
    Bs[lK + 2][lRow] = bv.z; Bs[lK + 3][lRow] = bv.w;
    __syncthreads();
#pragma unroll
    for (int kk = 0; kk < 8; kk++) {
      float ar[8], br[8];
      *(float4*)(ar)     = *(const float4*)&As[kk][ty * 8];
      *(float4*)(ar + 4) = *(const float4*)&As[kk][ty * 8 + 4];
      *(float4*)(br)     = *(const float4*)&Bs[kk][tx * 8];
      *(float4*)(br + 4) = *(const float4*)&Bs[kk][tx * 8 + 4];
#pragma unroll
      for (int i = 0; i < 8; i++)
#pragma unroll
        for (int j = 0; j < 8; j++) acc[i][j] += ar[i] * br[j];
    }
    __syncthreads();
  }

  const float C_OUT = 0.91914503001805780f;  // 0.7/sqrt(0.58)
  const float C_X   = 0.39391929857916763f;  // 0.3/sqrt(0.58)
#pragma unroll
  for (int i = 0; i < 8; i++) {
    const size_t r = (size_t)(m0 + ty * 8 + i);
    float* cp = C + r * NCOLS + n0 + tx * 8;
    if (FUSE) {
      const float* rp = resid + r * NCOLS + n0 + tx * 8;
#pragma unroll
      for (int j4 = 0; j4 < 2; j4++) {
        float4 rv = *(const float4*)(rp + j4 * 4);
        float4 ov;
        ov.x = acc[i][j4 * 4 + 0] * C_OUT + rv.x * C_X;
        ov.y = acc[i][j4 * 4 + 1] * C_OUT + rv.y * C_X;
        ov.z = acc[i][j4 * 4 + 2] * C_OUT + rv.z * C_X;
        ov.w = acc[i][j4 * 4 + 3] * C_OUT + rv.w * C_X;
        *(float4*)(cp + j4 * 4) = ov;
      }
    } else {
      *(float4*)(cp)     = make_float4(acc[i][0], acc[i][1], acc[i][2], acc[i][3]);
      *(float4*)(cp + 4) = make_float4(acc[i][4], acc[i][5], acc[i][6], acc[i][7]);
    }
  }
}

__global__ __launch_bounds__(256, 2) void qkv_gemm_kernel(const float* __restrict__ x) {
  sgemm_core<kQkvN, false>(x, g_wn_qkv, g_qkv, nullptr);
}

__global__ __launch_bounds__(256, 2) void out_gemm_kernel(const float* __restrict__ x,
                                                          float* __restrict__ outp) {
  sgemm_core<kDim, true>(g_attn, g_wn_out, outp, x);
}

// ---------------- flash attention, fp32, pixel-norm fused ----------------
// grid: (n/64, b*h); block 256. Per CTA: 64 q-rows for one (b,h).
// q_eff = q/max(||q||,eps)  (sqrt(d)*d^-0.5 cancels); k,v scaled by 8/max(||.||,eps).
__global__ __launch_bounds__(256, 2) void attn_kernel(const float* __restrict__ memkv) {
  __shared__ float Qs[64 * 64];
  __shared__ float Kts[64 * 64];  // normalized K^T; reused as P (row-major) after S
  __shared__ float Vs[64 * 64];

  const float* __restrict__ qkv = g_qkv;
  const int t  = threadIdx.x;
  const int tx = t & 15, ty = t >> 4;
  const int rr = t >> 2, qq = t & 3;   // load-phase: 4 threads per row
  const int qt = blockIdx.x;
  const int b  = blockIdx.y >> 4;
  const int h  = blockIdx.y & 15;

  // ---- load + pixel-norm Q tile ----
  {
    const float* qp = qkv + (size_t)(b * kN + qt * 64 + rr) * kQkvN + h * 64 + qq * 16;
    float4 v0 = *(const float4*)(qp + 0);
    float4 v1 = *(const float4*)(qp + 4);
    float4 v2 = *(const float4*)(qp + 8);
    float4 v3 = *(const float4*)(qp + 12);
    float ss = v0.x * v0.x + v0.y * v0.y + v0.z * v0.z + v0.w * v0.w
             + v1.x * v1.x + v1.y * v1.y + v1.z * v1.z + v1.w * v1.w
             + v2.x * v2.x + v2.y * v2.y + v2.z * v2.z + v2.w * v2.w
             + v3.x * v3.x + v3.y * v3.y + v3.z * v3.z + v3.w * v3.w;
    ss += __shfl_xor_sync(0xffffffffu, ss, 1);
    ss += __shfl_xor_sync(0xffffffffu, ss, 2);
    float sc = 1.0f / fmaxf(sqrtf(ss), 1e-4f);
    float* qd = &Qs[rr * 64 + qq * 16];
    *(float4*)(qd + 0)  = make_float4(v0.x * sc, v0.y * sc, v0.z * sc, v0.w * sc);
    *(float4*)(qd + 4)  = make_float4(v1.x * sc, v1.y * sc, v1.z * sc, v1.w * sc);
    *(float4*)(qd + 8)  = make_float4(v2.x * sc, v2.y * sc, v2.z * sc, v2.w * sc);
    *(float4*)(qd + 12) = make_float4(v3.x * sc, v3.y * sc, v3.z * sc, v3.w * sc);
  }

  float o[4][4];
  float mI[4], lI[4];
#pragma unroll
  for (int i = 0; i < 4; i++) {
    mI[i] = -INFINITY; lI[i] = 0.f;
#pragma unroll
    for (int j = 0; j < 4; j++) o[i][j] = 0.f;
  }

  for (int j0 = 0; j0 < kKV; j0 += 64) {
    const int L = (kKV - j0 < 64) ? (kKV - j0) : 64;
    const int j = j0 + rr;
    float kf[16], vf[16];
    float ssk = 0.f, ssv = 0.f;
    if (j < kKV) {
      const float *kp, *vp;
      if (j < 4) {  // memory kv slots
        kp = memkv + (size_t)(h * 4 + j) * 64 + qq * 16;
        vp = memkv + (size_t)((kHeads + h) * 4 + j) * 64 + qq * 16;
      } else {
        const size_t base = (size_t)(b * kN + (j - 4)) * kQkvN + h * 64 + qq * 16;
        kp = qkv + base + 1024;
        vp = qkv + base + 2048;
      }
#pragma unroll
      for (int u = 0; u < 4; u++) {
        float4 k4 = *(const float4*)(kp + u * 4);
        float4 v4 = *(const float4*)(vp + u * 4);
        kf[u * 4 + 0] = k4.x; kf[u * 4 + 1] = k4.y; kf[u * 4 + 2] = k4.z; kf[u * 4 + 3] = k4.w;
        vf[u * 4 + 0] = v4.x; vf[u * 4 + 1] = v4.y; vf[u * 4 + 2] = v4.z; vf[u * 4 + 3] = v4.w;
        ssk += k4.x * k4.x + k4.y * k4.y + k4.z * k4.z + k4.w * k4.w;
        ssv += v4.x * v4.x + v4.y * v4.y + v4.z * v4.z + v4.w * v4.w;
      }
    } else {
#pragma unroll
      for (int u = 0; u < 16; u++) { kf[u] = 0.f; vf[u] = 0.f; }
    }
    // reduce sumsq across the 4 loader lanes (shfl hoisted out of branch)
    ssk += __shfl_xor_sync(0xffffffffu, ssk, 1);
    ssk += __shfl_xor_sync(0xffffffffu, ssk, 2);
    ssv += __shfl_xor_sync(0xffffffffu, ssv, 1);
    ssv += __shfl_xor_sync(0xffffffffu, ssv, 2);
    const float sk = (j < kKV) ? 8.0f / fmaxf(sqrtf(ssk), 1e-4f) : 0.f;
    const float sv = (j < kKV) ? 8.0f / fmaxf(sqrtf(ssv), 1e-4f) : 0.f;

    __syncthreads();  // previous tile's Kts(P)/Vs fully consumed
    {
      float* vd = &Vs[rr * 64 + qq * 16];
#pragma unroll
      for (int u = 0; u < 4; u++)
        *(float4*)(vd + u * 4) = make_float4(vf[u * 4 + 0] * sv, vf[u * 4 + 1] * sv,
                                             vf[u * 4 + 2] * sv, vf[u * 4 + 3] * sv);
#pragma unroll
      for (int u = 0; u < 16; u++) Kts[(qq * 16 + u) * 64 + rr] = kf[u] * sk;
    }
    __syncthreads();

    // ---- S = Qn @ Kn^T  (thread: 4 q-rows x 4 kv-cols) ----
    float s[4][4];
#pragma unroll
    for (int i = 0; i < 4; i++)
#pragma unroll
      for (int jj = 0; jj < 4; jj++) s[i][jj] = 0.f;
#pragma unroll 16
    for (int kk = 0; kk < 64; kk++) {
      const float4 bv = *(const float4*)&Kts[kk * 64 + tx * 4];
      const float a0 = Qs[(ty * 4 + 0) * 64 + kk];
      const float a1 = Qs[(ty * 4 + 1) * 64 + kk];
      const float a2 = Qs[(ty * 4 + 2) * 64 + kk];
      const float a3 = Qs[(ty * 4 + 3) * 64 + kk];
      s[0][0] += a0 * bv.x; s[0][1] += a0 * bv.y; s[0][2] += a0 * bv.z; s[0][3] += a0 * bv.w;
      s[1][0] += a1 * bv.x; s[1][1] += a1 * bv.y; s[1][2] += a1 * bv.z; s[1][3] += a1 * bv.w;
      s[2][0] += a2 * bv.x; s[2][1] += a2 * bv.y; s[2][2] += a2 * bv.z; s[2][3] += a2 * bv.w;
      s[3][0] += a3 * bv.x; s[3][1] += a3 * bv.y; s[3][2] += a3 * bv.z; s[3][3] += a3 * bv.w;
    }
    if (L < 64) {
#pragma unroll
      for (int jj = 0; jj < 4; jj++)
        if (tx * 4 + jj >= L) {
          s[0][jj] = -1e30f; s[1][jj] = -1e30f; s[2][jj] = -1e30f; s[3][jj] = -1e30f;
        }
    }

    // ---- online softmax update (16 lanes per row-group) ----
#pragma unroll
    for (int i = 0; i < 4; i++) {
      float mx = fmaxf(fmaxf(s[i][0], s[i][1]), fmaxf(s[i][2], s[i][3]));
      mx = fmaxf(mx, __shfl_xor_sync(0xffffffffu, mx, 1));
      mx = fmaxf(mx, __shfl_xor_sync(0xffffffffu, mx, 2));
      mx = fmaxf(mx, __shfl_xor_sync(0xffffffffu, mx, 4));
      mx = fmaxf(mx, __shfl_xor_sync(0xffffffffu, mx, 8));
      const float mn = fmaxf(mI[i], mx);
      const float alpha = __expf(mI[i] - mn);
      mI[i] = mn;
      float rs = 0.f;
#pragma unroll
      for (int jj = 0; jj < 4; jj++) { s[i][jj] = __expf(s[i][jj] - mn); rs += s[i][jj]; }
      rs += __shfl_xor_sync(0xffffffffu, rs, 1);
      rs += __shfl_xor_sync(0xffffffffu, rs, 2);
      rs += __shfl_xor_sync(0xffffffffu, rs, 4);
      rs += __shfl_xor_sync(0xffffffffu, rs, 8);
      lI[i] = lI[i] * alpha + rs;
#pragma unroll
      for (int jj = 0; jj < 4; jj++) o[i][jj] *= alpha;
    }

    __syncthreads();  // everyone done reading Kts
#pragma unroll
    for (int i = 0; i < 4; i++)
      *(float4*)&Kts[(ty * 4 + i) * 64 + tx * 4] =
          make_float4(s[i][0], s[i][1], s[i][2], s[i][3]);  // P tile
    __syncthreads();

    // ---- O += P @ Vn ----
#pragma unroll 16
    for (int jj = 0; jj < 64; jj++) {
      const float4 vv = *(const float4*)&Vs[jj * 64 + tx * 4];
      const float p0 = Kts[(ty * 4 + 0) * 64 + jj];
      const float p1 = Kts[(ty * 4 + 1) * 64 + jj];
      const float p2 = Kts[(ty * 4 + 2) * 64 + jj];
      const float p3 = Kts[(ty * 4 + 3) * 64 + jj];
      o[0][0] += p0 * vv.x; o[0][1] += p0 * vv.y; o[0][2] += p0 * vv.z; o[0][3] += p0 * vv.w;
      o[1][0] += p1 * vv.x; o[1][1] += p1 * vv.y; o[1][2] += p1 * vv.z; o[1][3] += p1 * vv.w;
      o[2][0] += p2 * vv.x; o[2][1] += p2 * vv.y; o[2][2] += p2 * vv.z; o[2][3] += p2 * vv.w;
      o[3][0] += p3 * vv.x; o[3][1] += p3 * vv.y; o[3][2] += p3 * vv.z; o[3][3] += p3 * vv.w;
    }
  }

  // ---- write attn output [b, n, h*d] ----
#pragma unroll
  for (int i = 0; i < 4; i++) {
    const float inv = 1.0f / lI[i];
    *(float4*)&g_attn[(size_t)(b * kN + qt * 64 + ty * 4 + i) * kDim + h * 64 + tx * 4] =
        make_float4(o[i][0] * inv, o[i][1] * inv, o[i][2] * inv, o[i][3] * inv);
  }
}

// ---------------- launch ----------------
extern "C" void kernel_launch(void* const* d_in, const int* in_sizes, int n_in,
                              void* d_out, int out_size) {
  const float *x = nullptr, *wq = nullptr, *wo = nullptr, *mkv = nullptr;
  for (int i = 0; i < n_in; i++) {
    switch (in_sizes[i]) {
      case kRows * kDim:        x   = (const float*)d_in[i]; break;  // 4194304
      case kQkvN * kDim:        wq  = (const float*)d_in[i]; break;  // 3145728
      case kDim * kDim:         wo  = (const float*)d_in[i]; break;  // 1048576
      case 2 * kHeads * 4 * kD: mkv = (const float*)d_in[i]; break;  // 8192
    }
  }
  if (!x || !wq || !wo || !mkv) return;

  norm_rows_kernel<<<kQkvN, 256>>>(wq, 0);
  norm_rows_kernel<<<kDim, 256>>>(wo, 1);
  qkv_gemm_kernel<<<dim3(kQkvN / 128, kRows / 128), 256>>>(x);
  attn_kernel<<<dim3(kN / 64, kB * kHeads), 256>>>(mkv);
  out_gemm_kernel<<<dim3(kDim / 128, kRows / 128), 256>>>(x, (float*)d_out);
}

// round 9
// speedup vs baseline: 1.3404x; 1.3404x over previous
#include <cuda_runtime.h>
#include <math.h>
#include <stdint.h>

static constexpr int kHeads = 16;
static constexpr int kD     = 64;
static constexpr int kB     = 2;
static constexpr int kN     = 2048;
static constexpr int kDim   = 1024;
static constexpr int kRows  = kB * kN;          // 4096
static constexpr int kQkvN  = 3 * kHeads * kD;  // 3072
static constexpr int kKV    = kN + 4;           // 2052

// ---------------- scratch (device globals; no allocation) ----------------
__device__ float g_wn_qkv[(size_t)kQkvN * kDim];
__device__ float g_wn_out[(size_t)kDim * kDim];
__device__ float g_qkv[(size_t)kRows * kQkvN];
__device__ float g_attn[(size_t)kRows * kDim];
__device__ float g_x32[(size_t)kRows * kDim];   // tf32-rounded x

__device__ __forceinline__ float to_tf32(float x) {
  uint32_t u;
  asm("cvt.rna.tf32.f32 %0, %1;" : "=r"(u) : "f"(x));
  return __uint_as_float(u);
}

__device__ __forceinline__ void cp16(void* s, const void* g) {
  uint32_t sa = (uint32_t)__cvta_generic_to_shared(s);
  asm volatile("cp.async.cg.shared.global [%0], [%1], 16;\n" :: "r"(sa), "l"(g));
}

__device__ __forceinline__ void mma_tf32(float* d, const uint32_t* a, const uint32_t* b) {
  asm volatile(
      "mma.sync.aligned.m16n8k8.row.col.f32.tf32.tf32.f32 "
      "{%0,%1,%2,%3}, {%4,%5,%6,%7}, {%8,%9}, {%0,%1,%2,%3};\n"
      : "+f"(d[0]), "+f"(d[1]), "+f"(d[2]), "+f"(d[3])
      : "r"(a[0]), "r"(a[1]), "r"(a[2]), "r"(a[3]), "r"(b[0]), "r"(b[1]));
}

// ---------------- round x to tf32 ----------------
__global__ __launch_bounds__(256) void round_x_kernel(const float* __restrict__ x) {
  const int i = blockIdx.x * 256 + threadIdx.x;  // one float4 each
  float4 v = ((const float4*)x)[i];
  ((float4*)g_x32)[i] = make_float4(to_tf32(v.x), to_tf32(v.y), to_tf32(v.z), to_tf32(v.w));
}

// ---------------- weight row l2-norm (tf32-rounded output) ----------------
__global__ __launch_bounds__(256) void norm_rows_kernel(const float* __restrict__ w, int which) {
  float* wn = which ? g_wn_out : g_wn_qkv;
  const int row = blockIdx.x;
  const int t = threadIdx.x;  // 256 threads, 1024 cols -> 1 float4 each
  float4 v = ((const float4*)(w + (size_t)row * kDim))[t];
  float ss = v.x * v.x + v.y * v.y + v.z * v.z + v.w * v.w;
#pragma unroll
  for (int off = 16; off; off >>= 1) ss += __shfl_xor_sync(0xffffffffu, ss, off);
  __shared__ float red[8];
  if ((t & 31) == 0) red[t >> 5] = ss;
  __syncthreads();
  float tot = red[0] + red[1] + red[2] + red[3] + red[4] + red[5] + red[6] + red[7];
  float sc = 1.0f / (fmaxf(sqrtf(tot), 1e-4f) * 32.0f);  // 32 = sqrt(1024)
  ((float4*)(wn + (size_t)row * kDim))[t] =
      make_float4(to_tf32(v.x * sc), to_tf32(v.y * sc), to_tf32(v.z * sc), to_tf32(v.w * sc));
}

// ---------------- tf32 tensor-core GEMM: C[m,n] = sum_k A[m,k]*B[n,k] ----------------
// 128x128 CTA tile, BK=32, 8 warps (2x4), warp tile 64x32 = 4x4 m16n8k8 frags.
// smem: 2-stage A/B tiles, [128][36] padded (bank = 4r+c -> conflict-free frags).
template <int NCOLS, bool FUSE>
__global__ __launch_bounds__(256, 2) void gemm_tf32_kernel(const float* __restrict__ A,
                                                           const float* __restrict__ Bw,
                                                           float* __restrict__ C,
                                                           const float* __restrict__ resid) {
  extern __shared__ float sm[];
  float* AsBuf[2] = {sm, sm + 4608};
  float* BsBuf[2] = {sm + 9216, sm + 13824};

  const int t = threadIdx.x, lane = t & 31, warp = t >> 5;
  const int wm = warp >> 2, wn = warp & 3;
  const int m0 = blockIdx.y * 128, n0 = blockIdx.x * 128;
  const int srow = t >> 1, skc = (t & 1) * 16;
  const float* gA = A + (size_t)(m0 + srow) * kDim + skc;
  const float* gB = Bw + (size_t)(n0 + srow) * kDim + skc;

  auto prefetch = [&](int s, int k0) {
    float* da = AsBuf[s] + srow * 36 + skc;
    float* db = BsBuf[s] + srow * 36 + skc;
#pragma unroll
    for (int u = 0; u < 4; u++) {
      cp16(da + u * 4, gA + k0 + u * 4);
      cp16(db + u * 4, gB + k0 + u * 4);
    }
  };

  float acc[4][4][4];
#pragma unroll
  for (int mt = 0; mt < 4; mt++)
#pragma unroll
    for (int nt = 0; nt < 4; nt++)
#pragma unroll
      for (int r = 0; r < 4; r++) acc[mt][nt][r] = 0.f;

  prefetch(0, 0);
  asm volatile("cp.async.commit_group;\n");

  const int qr = lane >> 2, qc = lane & 3;

#pragma unroll 1
  for (int kb = 0; kb < 32; kb++) {
    const int cur = kb & 1;
    if (kb < 31) {
      prefetch(cur ^ 1, (kb + 1) * 32);
      asm volatile("cp.async.commit_group;\n");
      asm volatile("cp.async.wait_group 1;\n");
    } else {
      asm volatile("cp.async.wait_group 0;\n");
    }
    __syncthreads();

    const uint32_t* au = (const uint32_t*)AsBuf[cur];
    const uint32_t* bu = (const uint32_t*)BsBuf[cur];
#pragma unroll
    for (int kt = 0; kt < 4; kt++) {
      uint32_t af[4][4], bf[4][2];
      const int c = kt * 8 + qc;
#pragma unroll
      for (int mt = 0; mt < 4; mt++) {
        const int r = wm * 64 + mt * 16 + qr;
        af[mt][0] = au[r * 36 + c];
        af[mt][1] = au[(r + 8) * 36 + c];
        af[mt][2] = au[r * 36 + c + 4];
        af[mt][3] = au[(r + 8) * 36 + c + 4];
      }
#pragma unroll
      for (int nt = 0; nt < 4; nt++) {
        const int n = wn * 32 + nt * 8 + qr;
        bf[nt][0] = bu[n * 36 + c];
        bf[nt][1] = bu[n * 36 + c + 4];
      }
#pragma unroll
      for (int mt = 0; mt < 4; mt++)
#pragma unroll
        for (int nt = 0; nt < 4; nt++) mma_tf32(acc[mt][nt], af[mt], bf[nt]);
    }
    __syncthreads();
  }

  // epilogue: c-frag (r,cb),(r,cb+1),(r+8,cb),(r+8,cb+1)
  const float C_OUT = 0.91914503001805780f;  // 0.7/sqrt(0.58)
  const float C_X   = 0.39391929857916763f;  // 0.3/sqrt(0.58)
#pragma unroll
  for (int mt = 0; mt < 4; mt++)
#pragma unroll
    for (int nt = 0; nt < 4; nt++) {
      const int r = m0 + wm * 64 + mt * 16 + qr;
      const int cb = n0 + wn * 32 + nt * 8 + qc * 2;
      const float* a4 = acc[mt][nt];
      if (FUSE) {
        float2 r0 = *(const float2*)&resid[(size_t)r * NCOLS + cb];
        float2 r1 = *(const float2*)&resid[(size_t)(r + 8) * NCOLS + cb];
        *(float2*)&C[(size_t)r * NCOLS + cb] =
            make_float2(a4[0] * C_OUT + r0.x * C_X, a4[1] * C_OUT + r0.y * C_X);
        *(float2*)&C[(size_t)(r + 8) * NCOLS + cb] =
            make_float2(a4[2] * C_OUT + r1.x * C_X, a4[3] * C_OUT + r1.y * C_X);
      } else {
        *(float2*)&C[(size_t)r * NCOLS + cb] = make_float2(a4[0], a4[1]);
        *(float2*)&C[(size_t)(r + 8) * NCOLS + cb] = make_float2(a4[2], a4[3]);
      }
    }
}

// ---------------- flash attention, fp32, pixel-norm fused ----------------
// Qt[k][row] (stride 68) and Pt[kv][row] (stride 68) transposed in smem so both
// inner loops are 2x LDS.128 + 16 FFMA (FFMA-bound, not crossbar-bound).
static constexpr int kQtS = 68;
static constexpr int kAttnSmem = (64 * kQtS + 64 * 64 + 64 * 64 + 64 * kQtS);  // floats

__global__ __launch_bounds__(256, 2) void attn_kernel(const float* __restrict__ memkv) {
  extern __shared__ float sm[];
  float* Qt  = sm;                    // [64][68]  (Q^T, normalized)
  float* Kts = Qt + 64 * kQtS;        // [64][64]  (K^T, normalized)
  float* Vs  = Kts + 64 * 64;         // [64][64]
  float* Pt  = Vs + 64 * 64;          // [64][68]  (P^T)

  const float* __restrict__ qkv = g_qkv;
  const int t  = threadIdx.x;
  const int tx = t & 15, ty = t >> 4;
  const int rr = t >> 2, qq = t & 3;   // load-phase: 4 threads per row
  const int qt = blockIdx.x;
  const int b  = blockIdx.y >> 4;
  const int h  = blockIdx.y & 15;

  // ---- load + pixel-norm Q tile (store transposed) ----
  {
    const float* qp = qkv + (size_t)(b * kN + qt * 64 + rr) * kQkvN + h * 64 + qq * 16;
    float qv[16];
    float ss = 0.f;
#pragma unroll
    for (int u = 0; u < 4; u++) {
      float4 v = *(const float4*)(qp + u * 4);
      qv[u * 4 + 0] = v.x; qv[u * 4 + 1] = v.y; qv[u * 4 + 2] = v.z; qv[u * 4 + 3] = v.w;
      ss += v.x * v.x + v.y * v.y + v.z * v.z + v.w * v.w;
    }
    ss += __shfl_xor_sync(0xffffffffu, ss, 1);
    ss += __shfl_xor_sync(0xffffffffu, ss, 2);
    const float sc = 1.0f / fmaxf(sqrtf(ss), 1e-4f);
#pragma unroll
    for (int u = 0; u < 16; u++) Qt[(qq * 16 + u) * kQtS + rr] = qv[u] * sc;
  }

  float o[4][4];
  float mI[4], lI[4];
#pragma unroll
  for (int i = 0; i < 4; i++) {
    mI[i] = -INFINITY; lI[i] = 0.f;
#pragma unroll
    for (int j = 0; j < 4; j++) o[i][j] = 0.f;
  }

  for (int j0 = 0; j0 < kKV; j0 += 64) {
    const int L = (kKV - j0 < 64) ? (kKV - j0) : 64;
    const int j = j0 + rr;
    float kf[16], vf[16];
    float ssk = 0.f, ssv = 0.f;
    if (j < kKV) {
      const float *kp, *vp;
      if (j < 4) {  // memory kv slots
        kp = memkv + (size_t)(h * 4 + j) * 64 + qq * 16;
        vp = memkv + (size_t)((kHeads + h) * 4 + j) * 64 + qq * 16;
      } else {
        const size_t base = (size_t)(b * kN + (j - 4)) * kQkvN + h * 64 + qq * 16;
        kp = qkv + base + 1024;
        vp = qkv + base + 2048;
      }
#pragma unroll
      for (int u = 0; u < 4; u++) {
        float4 k4 = *(const float4*)(kp + u * 4);
        float4 v4 = *(const float4*)(vp + u * 4);
        kf[u * 4 + 0] = k4.x; kf[u * 4 + 1] = k4.y; kf[u * 4 + 2] = k4.z; kf[u * 4 + 3] = k4.w;
        vf[u * 4 + 0] = v4.x; vf[u * 4 + 1] = v4.y; vf[u * 4 + 2] = v4.z; vf[u * 4 + 3] = v4.w;
        ssk += k4.x * k4.x + k4.y * k4.y + k4.z * k4.z + k4.w * k4.w;
        ssv += v4.x * v4.x + v4.y * v4.y + v4.z * v4.z + v4.w * v4.w;
      }
    } else {
#pragma unroll
      for (int u = 0; u < 16; u++) { kf[u] = 0.f; vf[u] = 0.f; }
    }
    ssk += __shfl_xor_sync(0xffffffffu, ssk, 1);
    ssk += __shfl_xor_sync(0xffffffffu, ssk, 2);
    ssv += __shfl_xor_sync(0xffffffffu, ssv, 1);
    ssv += __shfl_xor_sync(0xffffffffu, ssv, 2);
    const float sk = (j < kKV) ? 8.0f / fmaxf(sqrtf(ssk), 1e-4f) : 0.f;
    const float sv = (j < kKV) ? 8.0f / fmaxf(sqrtf(ssv), 1e-4f) : 0.f;

    __syncthreads();  // previous tile fully consumed
    {
      float* vd = &Vs[rr * 64 + qq * 16];
#pragma unroll
      for (int u = 0; u < 4; u++)
        *(float4*)(vd + u * 4) = make_float4(vf[u * 4 + 0] * sv, vf[u * 4 + 1] * sv,
                                             vf[u * 4 + 2] * sv, vf[u * 4 + 3] * sv);
#pragma unroll
      for (int u = 0; u < 16; u++) Kts[(qq * 16 + u) * 64 + rr] = kf[u] * sk;
    }
    __syncthreads();

    // ---- S = Qn @ Kn^T : 2x LDS.128 + 16 FFMA per iter ----
    float s[4][4];
#pragma unroll
    for (int i = 0; i < 4; i++)
#pragma unroll
      for (int jj = 0; jj < 4; jj++) s[i][jj] = 0.f;
#pragma unroll 16
    for (int kk = 0; kk < 64; kk++) {
      const float4 aq = *(const float4*)&Qt[kk * kQtS + ty * 4];
      const float4 bk = *(const float4*)&Kts[kk * 64 + tx * 4];
      s[0][0] += aq.x * bk.x; s[0][1] += aq.x * bk.y; s[0][2] += aq.x * bk.z; s[0][3] += aq.x * bk.w;
      s[1][0] += aq.y * bk.x; s[1][1] += aq.y * bk.y; s[1][2] += aq.y * bk.z; s[1][3] += aq.y * bk.w;
      s[2][0] += aq.z * bk.x; s[2][1] += aq.z * bk.y; s[2][2] += aq.z * bk.z; s[2][3] += aq.z * bk.w;
      s[3][0] += aq.w * bk.x; s[3][1] += aq.w * bk.y; s[3][2] += aq.w * bk.z; s[3][3] += aq.w * bk.w;
    }
    if (L < 64) {
#pragma unroll
      for (int jj = 0; jj < 4; jj++)
        if (tx * 4 + jj >= L) {
          s[0][jj] = -1e30f; s[1][jj] = -1e30f; s[2][jj] = -1e30f; s[3][jj] = -1e30f;
        }
    }

    // ---- online softmax update ----
#pragma unroll
    for (int i = 0; i < 4; i++) {
      float mx = fmaxf(fmaxf(s[i][0], s[i][1]), fmaxf(s[i][2], s[i][3]));
      mx = fmaxf(mx, __shfl_xor_sync(0xffffffffu, mx, 1));
      mx = fmaxf(mx, __shfl_xor_sync(0xffffffffu, mx, 2));
      mx = fmaxf(mx, __shfl_xor_sync(0xffffffffu, mx, 4));
      mx = fmaxf(mx, __shfl_xor_sync(0xffffffffu, mx, 8));
      const float mn = fmaxf(mI[i], mx);
      const float alpha = __expf(mI[i] - mn);
      mI[i] = mn;
      float rs = 0.f;
#pragma unroll
      for (int jj = 0; jj < 4; jj++) { s[i][jj] = __expf(s[i][jj] - mn); rs += s[i][jj]; }
      rs += __shfl_xor_sync(0xffffffffu, rs, 1);
      rs += __shfl_xor_sync(0xffffffffu, rs, 2);
      rs += __shfl_xor_sync(0xffffffffu, rs, 4);
      rs += __shfl_xor_sync(0xffffffffu, rs, 8);
      lI[i] = lI[i] * alpha + rs;
#pragma unroll
      for (int jj = 0; jj < 4; jj++) o[i][jj] *= alpha;
    }

    // ---- write P transposed ----
#pragma unroll
    for (int jj = 0; jj < 4; jj++)
      *(float4*)&Pt[(tx * 4 + jj) * kQtS + ty * 4] =
          make_float4(s[0][jj], s[1][jj], s[2][jj], s[3][jj]);
    __syncthreads();

    // ---- O += P @ Vn : 2x LDS.128 + 16 FFMA per iter ----
#pragma unroll 16
    for (int jj = 0; jj < 64; jj++) {
      const float4 pp = *(const float4*)&Pt[jj * kQtS + ty * 4];
      const float4 vv = *(const float4*)&Vs[jj * 64 + tx * 4];
      o[0][0] += pp.x * vv.x; o[0][1] += pp.x * vv.y; o[0][2] += pp.x * vv.z; o[0][3] += pp.x * vv.w;
      o[1][0] += pp.y * vv.x; o[1][1] += pp.y * vv.y; o[1][2] += pp.y * vv.z; o[1][3] += pp.y * vv.w;
      o[2][0] += pp.z * vv.x; o[2][1] += pp.z * vv.y; o[2][2] += pp.z * vv.z; o[2][3] += pp.z * vv.w;
      o[3][0] += pp.w * vv.x; o[3][1] += pp.w * vv.y; o[3][2] += pp.w * vv.z; o[3][3] += pp.w * vv.w;
    }
  }

  // ---- write attn output [b, n, h*d], tf32-rounded for the tensor-core out-proj ----
#pragma unroll
  for (int i = 0; i < 4; i++) {
    const float inv = 1.0f / lI[i];
    *(float4*)&g_attn[(size_t)(b * kN + qt * 64 + ty * 4 + i) * kDim + h * 64 + tx * 4] =
        make_float4(to_tf32(o[i][0] * inv), to_tf32(o[i][1] * inv),
                    to_tf32(o[i][2] * inv), to_tf32(o[i][3] * inv));
  }
}

// ---------------- launch ----------------
extern "C" void kernel_launch(void* const* d_in, const int* in_sizes, int n_in,
                              void* d_out, int out_size) {
  const float *x = nullptr, *wq = nullptr, *wo = nullptr, *mkv = nullptr;
  for (int i = 0; i < n_in; i++) {
    switch (in_sizes[i]) {
      case kRows * kDim:        x   = (const float*)d_in[i]; break;  // 4194304
      case kQkvN * kDim:        wq  = (const float*)d_in[i]; break;  // 3145728
      case kDim * kDim:         wo  = (const float*)d_in[i]; break;  // 1048576
      case 2 * kHeads * 4 * kD: mkv = (const float*)d_in[i]; break;  // 8192
    }
  }
  if (!x || !wq || !wo || !mkv) return;

  static bool attr_set = false;
  if (!attr_set) {
    cudaFuncSetAttribute(gemm_tf32_kernel<kQkvN, false>,
                         cudaFuncAttributeMaxDynamicSharedMemorySize, 4 * 4608 * 4);
    cudaFuncSetAttribute(gemm_tf32_kernel<kDim, true>,
                         cudaFuncAttributeMaxDynamicSharedMemorySize, 4 * 4608 * 4);
    cudaFuncSetAttribute(attn_kernel,
                         cudaFuncAttributeMaxDynamicSharedMemorySize, kAttnSmem * 4);
    attr_set = true;
  }

  round_x_kernel<<<kRows * kDim / 1024, 256>>>(x);
  norm_rows_kernel<<<kQkvN, 256>>>(wq, 0);
  norm_rows_kernel<<<kDim, 256>>>(wo, 1);

  float* qkv_out = nullptr;  // g_qkv written via device-symbol reference inside kernel
  (void)qkv_out;

  // qkv = x32 @ wn_qkv^T
  {
    float* dummy;
    cudaGetSymbolAddress((void**)&dummy, g_qkv);  // resolved at capture time; host API, no alloc
    float* xin;
    cudaGetSymbolAddress((void**)&xin, g_x32);
    float* wnq;
    cudaGetSymbolAddress((void**)&wnq, g_wn_qkv);
    gemm_tf32_kernel<kQkvN, false><<<dim3(kQkvN / 128, kRows / 128), 256, 4 * 4608 * 4>>>(
        xin, wnq, dummy, nullptr);
  }

  attn_kernel<<<dim3(kN / 64, kB * kHeads), 256, kAttnSmem * 4>>>(mkv);

  // out = (attn @ wn_out^T) * c_out + x * c_x
  {
    float* attn_in;
    cudaGetSymbolAddress((void**)&attn_in, g_attn);
    float* wno;
    cudaGetSymbolAddress((void**)&wno, g_wn_out);
    gemm_tf32_kernel<kDim, true><<<dim3(kDim / 128, kRows / 128), 256, 4 * 4608 * 4>>>(
        attn_in, wno, (float*)d_out, x);
  }
}

// round 11
// speedup vs baseline: 2.5632x; 1.9122x over previous
#include <cuda_runtime.h>
#include <math.h>
#include <stdint.h>

static constexpr int kHeads = 16;
static constexpr int kD     = 64;
static constexpr int kB     = 2;
static constexpr int kN     = 2048;
static constexpr int kDim   = 1024;
static constexpr int kRows  = kB * kN;          // 4096
static constexpr int kQkvN  = 3 * kHeads * kD;  // 3072
static constexpr int kKV    = kN + 4;           // 2052

// ---------------- scratch (device globals; no allocation) ----------------
__device__ float g_wn_qkv[(size_t)kQkvN * kDim];
__device__ float g_wn_out[(size_t)kDim * kDim];
__device__ float g_qkv[(size_t)kRows * kQkvN];
__device__ float g_attn[(size_t)kRows * kDim];
__device__ float g_x32[(size_t)kRows * kDim];   // tf32-rounded x

__device__ __forceinline__ float to_tf32(float x) {
  uint32_t u;
  asm("cvt.rna.tf32.f32 %0, %1;" : "=r"(u) : "f"(x));
  return __uint_as_float(u);
}

__device__ __forceinline__ void cp16(void* s, const void* g) {
  uint32_t sa = (uint32_t)__cvta_generic_to_shared(s);
  asm volatile("cp.async.cg.shared.global [%0], [%1], 16;\n" :: "r"(sa), "l"(g));
}

__device__ __forceinline__ void mma_tf32(float* d, const uint32_t* a, const uint32_t* b) {
  asm volatile(
      "mma.sync.aligned.m16n8k8.row.col.f32.tf32.tf32.f32 "
      "{%0,%1,%2,%3}, {%4,%5,%6,%7}, {%8,%9}, {%0,%1,%2,%3};\n"
      : "+f"(d[0]), "+f"(d[1]), "+f"(d[2]), "+f"(d[3])
      : "r"(a[0]), "r"(a[1]), "r"(a[2]), "r"(a[3]), "r"(b[0]), "r"(b[1]));
}

// ---------------- round x to tf32 ----------------
__global__ __launch_bounds__(256) void round_x_kernel(const float* __restrict__ x) {
  const int i = blockIdx.x * 256 + threadIdx.x;  // one float4 each
  float4 v = ((const float4*)x)[i];
  ((float4*)g_x32)[i] = make_float4(to_tf32(v.x), to_tf32(v.y), to_tf32(v.z), to_tf32(v.w));
}

// ---------------- weight row l2-norm (tf32-rounded output) ----------------
__global__ __launch_bounds__(256) void norm_rows_kernel(const float* __restrict__ w, int which) {
  float* wn = which ? g_wn_out : g_wn_qkv;
  const int row = blockIdx.x;
  const int t = threadIdx.x;  // 256 threads, 1024 cols -> 1 float4 each
  float4 v = ((const float4*)(w + (size_t)row * kDim))[t];
  float ss = v.x * v.x + v.y * v.y + v.z * v.z + v.w * v.w;
#pragma unroll
  for (int off = 16; off; off >>= 1) ss += __shfl_xor_sync(0xffffffffu, ss, off);
  __shared__ float red[8];
  if ((t & 31) == 0) red[t >> 5] = ss;
  __syncthreads();
  float tot = red[0] + red[1] + red[2] + red[3] + red[4] + red[5] + red[6] + red[7];
  float sc = 1.0f / (fmaxf(sqrtf(tot), 1e-4f) * 32.0f);  // 32 = sqrt(1024)
  ((float4*)(wn + (size_t)row * kDim))[t] =
      make_float4(to_tf32(v.x * sc), to_tf32(v.y * sc), to_tf32(v.z * sc), to_tf32(v.w * sc));
}

// ---------------- tf32 tensor-core GEMM: C[m,n] = sum_k A[m,k]*B[n,k] ----------------
template <int NCOLS, bool FUSE>
__global__ __launch_bounds__(256, 2) void gemm_tf32_kernel(const float* __restrict__ A,
                                                           const float* __restrict__ Bw,
                                                           float* __restrict__ C,
                                                           const float* __restrict__ resid) {
  extern __shared__ float sm[];
  float* AsBuf[2] = {sm, sm + 4608};
  float* BsBuf[2] = {sm + 9216, sm + 13824};

  const int t = threadIdx.x, lane = t & 31, warp = t >> 5;
  const int wm = warp >> 2, wn = warp & 3;
  const int m0 = blockIdx.y * 128, n0 = blockIdx.x * 128;
  const int srow = t >> 1, skc = (t & 1) * 16;
  const float* gA = A + (size_t)(m0 + srow) * kDim + skc;
  const float* gB = Bw + (size_t)(n0 + srow) * kDim + skc;

  auto prefetch = [&](int s, int k0) {
    float* da = AsBuf[s] + srow * 36 + skc;
    float* db = BsBuf[s] + srow * 36 + skc;
#pragma unroll
    for (int u = 0; u < 4; u++) {
      cp16(da + u * 4, gA + k0 + u * 4);
      cp16(db + u * 4, gB + k0 + u * 4);
    }
  };

  float acc[4][4][4];
#pragma unroll
  for (int mt = 0; mt < 4; mt++)
#pragma unroll
    for (int nt = 0; nt < 4; nt++)
#pragma unroll
      for (int r = 0; r < 4; r++) acc[mt][nt][r] = 0.f;

  prefetch(0, 0);
  asm volatile("cp.async.commit_group;\n");

  const int qr = lane >> 2, qc = lane & 3;

#pragma unroll 1
  for (int kb = 0; kb < 32; kb++) {
    const int cur = kb & 1;
    if (kb < 31) {
      prefetch(cur ^ 1, (kb + 1) * 32);
      asm volatile("cp.async.commit_group;\n");
      asm volatile("cp.async.wait_group 1;\n");
    } else {
      asm volatile("cp.async.wait_group 0;\n");
    }
    __syncthreads();

    const uint32_t* au = (const uint32_t*)AsBuf[cur];
    const uint32_t* bu = (const uint32_t*)BsBuf[cur];
#pragma unroll
    for (int kt = 0; kt < 4; kt++) {
      uint32_t af[4][4], bf[4][2];
      const int c = kt * 8 + qc;
#pragma unroll
      for (int mt = 0; mt < 4; mt++) {
        const int r = wm * 64 + mt * 16 + qr;
        af[mt][0] = au[r * 36 + c];
        af[mt][1] = au[(r + 8) * 36 + c];
        af[mt][2] = au[r * 36 + c + 4];
        af[mt][3] = au[(r + 8) * 36 + c + 4];
      }
#pragma unroll
      for (int nt = 0; nt < 4; nt++) {
        const int n = wn * 32 + nt * 8 + qr;
        bf[nt][0] = bu[n * 36 + c];
        bf[nt][1] = bu[n * 36 + c + 4];
      }
#pragma unroll
      for (int mt = 0; mt < 4; mt++)
#pragma unroll
        for (int nt = 0; nt < 4; nt++) mma_tf32(acc[mt][nt], af[mt], bf[nt]);
    }
    __syncthreads();
  }

  const float C_OUT = 0.91914503001805780f;  // 0.7/sqrt(0.58)
  const float C_X   = 0.39391929857916763f;  // 0.3/sqrt(0.58)
#pragma unroll
  for (int mt = 0; mt < 4; mt++)
#pragma unroll
    for (int nt = 0; nt < 4; nt++) {
      const int r = m0 + wm * 64 + mt * 16 + qr;
      const int cb = n0 + wn * 32 + nt * 8 + qc * 2;
      const float* a4 = acc[mt][nt];
      if (FUSE) {
        float2 r0 = *(const float2*)&resid[(size_t)r * NCOLS + cb];
        float2 r1 = *(const float2*)&resid[(size_t)(r + 8) * NCOLS + cb];
        *(float2*)&C[(size_t)r * NCOLS + cb] =
            make_float2(a4[0] * C_OUT + r0.x * C_X, a4[1] * C_OUT + r0.y * C_X);
        *(float2*)&C[(size_t)(r + 8) * NCOLS + cb] =
            make_float2(a4[2] * C_OUT + r1.x * C_X, a4[3] * C_OUT + r1.y * C_X);
      } else {
        *(float2*)&C[(size_t)r * NCOLS + cb] = make_float2(a4[0], a4[1]);
        *(float2*)&C[(size_t)(r + 8) * NCOLS + cb] = make_float2(a4[2], a4[3]);
      }
    }
}

// ---------------- tensor-core flash attention (tf32 mma), pixel-norm fused ----------------
// CTA: 128 q-rows of one (b,h); 8 warps, warp w owns q-rows [w*16, w*16+16).
// KV tile 64. Smem: Ks [64][68] (K, natural = B-frag layout for S),
// Vt [64][68] (V^T, swizzled: col ^= ((d>>4)&3)<<3 -> conflict-free STS + loads),
// Pw per-warp [16][72] (swizzle col ^= ((row>>2)&1)<<2 -> conflict-free STS.64 + A-frag LDS).
static constexpr int kKsS = 68;
static constexpr int kPwS = 72;
static constexpr int kAttnSmemFloats = 2 * 64 * kKsS + 8 * 16 * kPwS;  // 17920
static constexpr int kAttnSmemBytes  = kAttnSmemFloats * 4;            // 71680

__global__ __launch_bounds__(256, 2) void attn_kernel(const float* __restrict__ memkv) {
  extern __shared__ float sm[];
  float* Ks = sm;                   // [64][68]
  float* Vt = sm + 64 * kKsS;       // [64][68]
  float* Pw = sm + 2 * 64 * kKsS;   // 8 x [16][72]

  const float* __restrict__ qkv = g_qkv;
  const int t = threadIdx.x;
  const int lane = t & 31, warp = t >> 5;
  const int qr = lane >> 2, qc = lane & 3;
  const int qt = blockIdx.x;
  const int b = blockIdx.y >> 4, h = blockIdx.y & 15;

  // ---- stage + pixel-norm Q (128 rows; rows 0-63 in Ks, 64-127 in Vt) ----
  {
    const int rr = t >> 1, half = t & 1;  // 2 threads per row, 32 cols each
    const float* qp = qkv + (size_t)(b * kN + qt * 128 + rr) * kQkvN + h * 64 + half * 32;
    float4 q4[8];
    float ss = 0.f;
#pragma unroll
    for (int u = 0; u < 8; u++) {
      q4[u] = *(const float4*)(qp + u * 4);
      ss += q4[u].x * q4[u].x + q4[u].y * q4[u].y + q4[u].z * q4[u].z + q4[u].w * q4[u].w;
    }
    ss += __shfl_xor_sync(0xffffffffu, ss, 1);
    const float sc = 1.0f / fmaxf(sqrtf(ss), 1e-4f);
    float* dst = ((rr < 64) ? Ks + rr * kKsS : Vt + (rr - 64) * kKsS) + half * 32;
#pragma unroll
    for (int u = 0; u < 8; u++)
      *(float4*)(dst + u * 4) = make_float4(to_tf32(q4[u].x * sc), to_tf32(q4[u].y * sc),
                                            to_tf32(q4[u].z * sc), to_tf32(q4[u].w * sc));
  }
  __syncthreads();

  // ---- load Q A-fragments into registers (held entire kernel) ----
  uint32_t qf[8][4];
  {
    const int m = warp * 16 + qr;
    const uint32_t* base =
        (const uint32_t*)((m < 64) ? Ks + m * kKsS : Vt + (m - 64) * kKsS);
#pragma unroll
    for (int kc = 0; kc < 8; kc++) {
      qf[kc][0] = base[kc * 8 + qc];
      qf[kc][1] = base[8 * kKsS + kc * 8 + qc];
      qf[kc][2] = base[kc * 8 + qc + 4];
      qf[kc][3] = base[8 * kKsS + kc * 8 + qc + 4];
    }
  }

  float oacc[8][4];
#pragma unroll
  for (int nt = 0; nt < 8; nt++)
#pragma unroll
    for (int r = 0; r < 4; r++) oacc[nt][r] = 0.f;
  float mr0 = -INFINITY, mr1 = -INFINITY, lr0 = 0.f, lr1 = 0.f;

  const int lr = t >> 2, lq = t & 3;  // kv load phase: 4 threads per row, 16 cols each

  for (int j0 = 0; j0 < kKV; j0 += 64) {
    const int L = (kKV - j0 < 64) ? (kKV - j0) : 64;
    const int j = j0 + lr;
    float kf[16], vf[16];
    float ssk = 0.f, ssv = 0.f;
    if (j < kKV) {
      const float *kp, *vp;
      if (j < 4) {  // memory kv slots
        kp = memkv + (size_t)(h * 4 + j) * 64 + lq * 16;
        vp = memkv + (size_t)((kHeads + h) * 4 + j) * 64 + lq * 16;
      } else {
        const size_t base = (size_t)(b * kN + (j - 4)) * kQkvN + h * 64 + lq * 16;
        kp = qkv + base + 1024;
        vp = qkv + base + 2048;
      }
#pragma unroll
      for (int u = 0; u < 4; u++) {
        float4 k4 = *(const float4*)(kp + u * 4);
        float4 v4 = *(const float4*)(vp + u * 4);
        kf[u * 4 + 0] = k4.x; kf[u * 4 + 1] = k4.y; kf[u * 4 + 2] = k4.z; kf[u * 4 + 3] = k4.w;
        vf[u * 4 + 0] = v4.x; vf[u * 4 + 1] = v4.y; vf[u * 4 + 2] = v4.z; vf[u * 4 + 3] = v4.w;
        ssk += k4.x * k4.x + k4.y * k4.y + k4.z * k4.z + k4.w * k4.w;
        ssv += v4.x * v4.x + v4.y * v4.y + v4.z * v4.z + v4.w * v4.w;
      }
    } else {
#pragma unroll
      for (int u = 0; u < 16; u++) { kf[u] = 0.f; vf[u] = 0.f; }
    }
    ssk += __shfl_xor_sync(0xffffffffu, ssk, 1);
    ssk += __shfl_xor_sync(0xffffffffu, ssk, 2);
    ssv += __shfl_xor_sync(0xffffffffu, ssv, 1);
    ssv += __shfl_xor_sync(0xffffffffu, ssv, 2);
    const float sk = (j < kKV) ? 8.0f / fmaxf(sqrtf(ssk), 1e-4f) : 0.f;
    const float sv = (j < kKV) ? 8.0f / fmaxf(sqrtf(ssv), 1e-4f) : 0.f;

    __syncthreads();  // previous tile (and Q-frag loads on iter 0) fully consumed
    {
      float* kd = Ks + lr * kKsS + lq * 16;
#pragma unroll
      for (int u = 0; u < 4; u++)
        *(float4*)(kd + u * 4) =
            make_float4(to_tf32(kf[u * 4 + 0] * sk), to_tf32(kf[u * 4 + 1] * sk),
                        to_tf32(kf[u * 4 + 2] * sk), to_tf32(kf[u * 4 + 3] * sk));
#pragma unroll
      for (int u = 0; u < 16; u++) {
        const int d = lq * 16 + u;
        Vt[d * kKsS + (lr ^ (((d >> 4) & 3) << 3))] = to_tf32(vf[u] * sv);
      }
    }
    __syncthreads();

    // ---- S = Qn @ Kn^T via mma (per warp: m16 x n64 x k64) ----
    float sf[8][4];
#pragma unroll
    for (int nt = 0; nt < 8; nt++)
#pragma unroll
      for (int r = 0; r < 4; r++) sf[nt][r] = 0.f;
    {
      const uint32_t* ku = (const uint32_t*)Ks;
#pragma unroll
      for (int nt = 0; nt < 8; nt++) {
        const int n = nt * 8 + qr;
#pragma unroll
        for (int kc = 0; kc < 8; kc++) {
          uint32_t bfr[2];
          bfr[0] = ku[n * kKsS + kc * 8 + qc];
          bfr[1] = ku[n * kKsS + kc * 8 + qc + 4];
          mma_tf32(sf[nt], qf[kc], bfr);
        }
      }
    }
    if (L < 64) {
#pragma unroll
      for (int nt = 0; nt < 8; nt++) {
        const int c0 = nt * 8 + 2 * qc;
        if (c0 >= L)     { sf[nt][0] = -1e30f; sf[nt][2] = -1e30f; }
        if (c0 + 1 >= L) { sf[nt][1] = -1e30f; sf[nt][3] = -1e30f; }
      }
    }

    // ---- online softmax on c-fragments (thread owns rows qr, qr+8; 16 cols each) ----
    {
      float mx0 = -INFINITY, mx1 = -INFINITY;
#pragma unroll
      for (int nt = 0; nt < 8; nt++) {
        mx0 = fmaxf(mx0, fmaxf(sf[nt][0], sf[nt][1]));
        mx1 = fmaxf(mx1, fmaxf(sf[nt][2], sf[nt][3]));
      }
      mx0 = fmaxf(mx0, __shfl_xor_sync(0xffffffffu, mx0, 1));
      mx0 = fmaxf(mx0, __shfl_xor_sync(0xffffffffu, mx0, 2));
      mx1 = fmaxf(mx1, __shfl_xor_sync(0xffffffffu, mx1, 1));
      mx1 = fmaxf(mx1, __shfl_xor_sync(0xffffffffu, mx1, 2));
      const float mn0 = fmaxf(mr0, mx0), mn1 = fmaxf(mr1, mx1);
      const float a0 = __expf(mr0 - mn0), a1 = __expf(mr1 - mn1);
      mr0 = mn0; mr1 = mn1;
      float rs0 = 0.f, rs1 = 0.f;
#pragma unroll
      for (int nt = 0; nt < 8; nt++) {
        sf[nt][0] = __expf(sf[nt][0] - mn0); rs0 += sf[nt][0];
        sf[nt][1] = __expf(sf[nt][1] - mn0); rs0 += sf[nt][1];
        sf[nt][2] = __expf(sf[nt][2] - mn1); rs1 += sf[nt][2];
        sf[nt][3] = __expf(sf[nt][3] - mn1); rs1 += sf[nt][3];
      }
      rs0 += __shfl_xor_sync(0xffffffffu, rs0, 1);
      rs0 += __shfl_xor_sync(0xffffffffu, rs0, 2);
      rs1 += __shfl_xor_sync(0xffffffffu, rs1, 1);
      rs1 += __shfl_xor_sync(0xffffffffu, rs1, 2);
      lr0 = lr0 * a0 + rs0;
      lr1 = lr1 * a1 + rs1;
#pragma unroll
      for (int nt = 0; nt < 8; nt++) {
        oacc[nt][0] *= a0; oacc[nt][1] *= a0;
        oacc[nt][2] *= a1; oacc[nt][3] *= a1;
      }
    }

    // ---- P c-frag -> smem (per-warp slab) -> A-frag; then O += P @ Vn ----
    {
      float* pw = Pw + warp * 16 * kPwS;
      const int sw0 = ((qr >> 2) & 1) << 2;  // row bit-2 swizzle (rows qr and qr+8 share it)
#pragma unroll
      for (int nt = 0; nt < 8; nt++) {
        const int col = (nt * 8 + 2 * qc) ^ sw0;
        *(float2*)&pw[qr * kPwS + col] =
            make_float2(to_tf32(sf[nt][0]), to_tf32(sf[nt][1]));
        *(float2*)&pw[(qr + 8) * kPwS + col] =
            make_float2(to_tf32(sf[nt][2]), to_tf32(sf[nt][3]));
      }
      __syncwarp();
      const uint32_t* pu = (const uint32_t*)pw;
      const uint32_t* vu = (const uint32_t*)Vt;
#pragma unroll
      for (int kc = 0; kc < 8; kc++) {
        uint32_t pa[4];
        pa[0] = pu[qr * kPwS + ((kc * 8 + qc) ^ sw0)];
        pa[1] = pu[(qr + 8) * kPwS + ((kc * 8 + qc) ^ sw0)];
        pa[2] = pu[qr * kPwS + ((kc * 8 + qc + 4) ^ sw0)];
        pa[3] = pu[(qr + 8) * kPwS + ((kc * 8 + qc + 4) ^ sw0)];
#pragma unroll
        for (int nt = 0; nt < 8; nt++) {
          const int n = nt * 8 + qr;
          const int vswz = ((n >> 4) & 3) << 3;
          uint32_t bfr[2];
          bfr[0] = vu[n * kKsS + ((kc * 8 + qc) ^ vswz)];
          bfr[1] = vu[n * kKsS + ((kc * 8 + qc + 4) ^ vswz)];
          mma_tf32(oacc[nt], pa, bfr);
        }
      }
    }
  }

  // ---- epilogue: normalize and write g_attn [b,n,h*d], tf32-rounded ----
  {
    const float i0 = 1.0f / lr0, i1 = 1.0f / lr1;
    const size_t r0 = (size_t)(b * kN + qt * 128 + warp * 16 + qr);
#pragma unroll
    for (int nt = 0; nt < 8; nt++) {
      const int col = h * 64 + nt * 8 + 2 * qc;
      *(float2*)&g_attn[r0 * kDim + col] =
          make_float2(to_tf32(oacc[nt][0] * i0), to_tf32(oacc[nt][1] * i0));
      *(float2*)&g_attn[(r0 + 8) * kDim + col] =
          make_float2(to_tf32(oacc[nt][2] * i1), to_tf32(oacc[nt][3] * i1));
    }
  }
}

// ---------------- launch ----------------
extern "C" void kernel_launch(void* const* d_in, const int* in_sizes, int n_in,
                              void* d_out, int out_size) {
  const float *x = nullptr, *wq = nullptr, *wo = nullptr, *mkv = nullptr;
  for (int i = 0; i < n_in; i++) {
    switch (in_sizes[i]) {
      case kRows * kDim:        x   = (const float*)d_in[i]; break;  // 4194304
      case kQkvN * kDim:        wq  = (const float*)d_in[i]; break;  // 3145728
      case kDim * kDim:         wo  = (const float*)d_in[i]; break;  // 1048576
      case 2 * kHeads * 4 * kD: mkv = (const float*)d_in[i]; break;  // 8192
    }
  }
  if (!x || !wq || !wo || !mkv) return;

  static bool attr_set = false;
  if (!attr_set) {
    cudaFuncSetAttribute(gemm_tf32_kernel<kQkvN, false>,
                         cudaFuncAttributeMaxDynamicSharedMemorySize, 4 * 4608 * 4);
    cudaFuncSetAttribute(gemm_tf32_kernel<kDim, true>,
                         cudaFuncAttributeMaxDynamicSharedMemorySize, 4 * 4608 * 4);
    cudaFuncSetAttribute(attn_kernel,
                         cudaFuncAttributeMaxDynamicSharedMemorySize, kAttnSmemBytes);
    attr_set = true;
  }

  round_x_kernel<<<kRows * kDim / 1024, 256>>>(x);
  norm_rows_kernel<<<kQkvN, 256>>>(wq, 0);
  norm_rows_kernel<<<kDim, 256>>>(wo, 1);

  // qkv = x32 @ wn_qkv^T
  {
    float* dummy;
    cudaGetSymbolAddress((void**)&dummy, g_qkv);
    float* xin;
    cudaGetSymbolAddress((void**)&xin, g_x32);
    float* wnq;
    cudaGetSymbolAddress((void**)&wnq, g_wn_qkv);
    gemm_tf32_kernel<kQkvN, false><<<dim3(kQkvN / 128, kRows / 128), 256, 4 * 4608 * 4>>>(
        xin, wnq, dummy, nullptr);
  }

  attn_kernel<<<dim3(kN / 128, kB * kHeads), 256, kAttnSmemBytes>>>(mkv);

  // out = (attn @ wn_out^T) * c_out + x * c_x
  {
    float* attn_in;
    cudaGetSymbolAddress((void**)&attn_in, g_attn);
    float* wno;
    cudaGetSymbolAddress((void**)&wno, g_wn_out);
    gemm_tf32_kernel<kDim, true><<<dim3(kDim / 128, kRows / 128), 256, 4 * 4608 * 4>>>(
        attn_in, wno, (float*)d_out, x);
  }
}

// round 14
// speedup vs baseline: 4.4900x; 1.7518x over previous
#include <cuda_runtime.h>
#include <cuda_bf16.h>
#include <math.h>
#include <stdint.h>

static constexpr int kHeads = 16;
static constexpr int kD     = 64;
static constexpr int kB     = 2;
static constexpr int kN     = 2048;
static constexpr int kDim   = 1024;
static constexpr int kRows  = kB * kN;          // 4096
static constexpr int kQkvN  = 3 * kHeads * kD;  // 3072
static constexpr int kKV    = kN + 4;           // 2052

// ---------------- scratch (device globals; no allocation) ----------------
__device__ __nv_bfloat16 g_x16[(size_t)kRows * kDim];
__device__ __nv_bfloat16 g_wn_qkv16[(size_t)kQkvN * kDim];
__device__ __nv_bfloat16 g_wn_out16[(size_t)kDim * kDim];
__device__ __nv_bfloat16 g_attn16[(size_t)kRows * kDim];
__device__ float g_qkv[(size_t)kRows * kQkvN];

__device__ __forceinline__ uint32_t bfpack(float lo, float hi) {
  uint32_t r;
  asm("cvt.rn.bf16x2.f32 %0, %1, %2;" : "=r"(r) : "f"(hi), "f"(lo));
  return r;
}

__device__ __forceinline__ void cp16(uint32_t* s, const void* g) {
  uint32_t sa = (uint32_t)__cvta_generic_to_shared(s);
  asm volatile("cp.async.cg.shared.global [%0], [%1], 16;\n" :: "r"(sa), "l"(g));
}

__device__ __forceinline__ void mma_bf16(float* d, const uint32_t* a, const uint32_t* b) {
  asm volatile(
      "mma.sync.aligned.m16n8k16.row.col.f32.bf16.bf16.f32 "
      "{%0,%1,%2,%3}, {%4,%5,%6,%7}, {%8,%9}, {%0,%1,%2,%3};\n"
      : "+f"(d[0]), "+f"(d[1]), "+f"(d[2]), "+f"(d[3])
      : "r"(a[0]), "r"(a[1]), "r"(a[2]), "r"(a[3]), "r"(b[0]), "r"(b[1]));
}

// ---------------- convert x to bf16 ----------------
__global__ __launch_bounds__(256) void conv_x_kernel(const float* __restrict__ x) {
  const int i = blockIdx.x * 256 + threadIdx.x;  // one float4 each
  float4 v = ((const float4*)x)[i];
  ((uint2*)g_x16)[i] = make_uint2(bfpack(v.x, v.y), bfpack(v.z, v.w));
}

// ---------------- weight row l2-norm -> bf16 ----------------
__global__ __launch_bounds__(256) void norm_rows_kernel(const float* __restrict__ w, int which) {
  __nv_bfloat16* wn = which ? g_wn_out16 : g_wn_qkv16;
  const int row = blockIdx.x;
  const int t = threadIdx.x;  // 256 threads, 1024 cols -> 1 float4 each
  float4 v = ((const float4*)(w + (size_t)row * kDim))[t];
  float ss = v.x * v.x + v.y * v.y + v.z * v.z + v.w * v.w;
#pragma unroll
  for (int off = 16; off; off >>= 1) ss += __shfl_xor_sync(0xffffffffu, ss, off);
  __shared__ float red[8];
  if ((t & 31) == 0) red[t >> 5] = ss;
  __syncthreads();
  float tot = red[0] + red[1] + red[2] + red[3] + red[4] + red[5] + red[6] + red[7];
  float sc = 1.0f / (fmaxf(sqrtf(tot), 1e-4f) * 32.0f);  // 32 = sqrt(1024)
  ((uint2*)(wn + (size_t)row * kDim))[t] =
      make_uint2(bfpack(v.x * sc, v.y * sc), bfpack(v.z * sc, v.w * sc));
}

// ---------------- bf16 tensor-core GEMM: C[m,n] = sum_k A[m,k]*B[n,k] ----------------
// 128x128 CTA tile, BK=64 halves (32 half2 = 128B/row), 2-stage cp.async,
// 8 warps (2x4), warp tile 64x32 = 4x4 m16n8k16 frags. smem stride 36 (half2/uint
// units) -> fragment loads hit 32 distinct banks ((4*qr+qc)%32).
template <int NCOLS, bool FUSE>
__global__ __launch_bounds__(256, 2) void gemm_bf16_kernel(const __nv_bfloat16* __restrict__ A,
                                                           const __nv_bfloat16* __restrict__ Bw,
                                                           float* __restrict__ C,
                                                           const float* __restrict__ resid) {
  extern __shared__ uint32_t sg[];
  uint32_t* AsBuf[2] = {sg, sg + 4608};
  uint32_t* BsBuf[2] = {sg + 9216, sg + 13824};

  const int t = threadIdx.x, lane = t & 31, warp = t >> 5;
  const int wm = warp >> 2, wn = warp & 3;
  const int m0 = blockIdx.y * 128, n0 = blockIdx.x * 128;
  const int srow = t >> 1, sc2 = (t & 1) * 16;  // half2 col offset
  const __nv_bfloat16* gA = A + (size_t)(m0 + srow) * kDim + sc2 * 2;
  const __nv_bfloat16* gB = Bw + (size_t)(n0 + srow) * kDim + sc2 * 2;

  auto prefetch = [&](int s, int k0) {  // k0 in halves
    uint32_t* da = AsBuf[s] + srow * 36 + sc2;
    uint32_t* db = BsBuf[s] + srow * 36 + sc2;
#pragma unroll
    for (int u = 0; u < 4; u++) {
      cp16(da + u * 4, gA + k0 + u * 8);
      cp16(db + u * 4, gB + k0 + u * 8);
    }
  };

  float acc[4][4][4];
#pragma unroll
  for (int mt = 0; mt < 4; mt++)
#pragma unroll
    for (int nt = 0; nt < 4; nt++)
#pragma unroll
      for (int r = 0; r < 4; r++) acc[mt][nt][r] = 0.f;

  prefetch(0, 0);
  asm volatile("cp.async.commit_group;\n");

  const int qr = lane >> 2, qc = lane & 3;

#pragma unroll 1
  for (int kb = 0; kb < 16; kb++) {  // 16 x 64 halves = 1024
    const int cur = kb & 1;
    if (kb < 15) {
      prefetch(cur ^ 1, (kb + 1) * 64);
      asm volatile("cp.async.commit_group;\n");
      asm volatile("cp.async.wait_group 1;\n");
    } else {
      asm volatile("cp.async.wait_group 0;\n");
    }
    __syncthreads();

    const uint32_t* au = AsBuf[cur];
    const uint32_t* bu = BsBuf[cur];
#pragma unroll
    for (int kt = 0; kt < 4; kt++) {  // 4 x k16
      uint32_t af[4][4], bf[4][2];
      const int c = kt * 8 + qc;
#pragma unroll
      for (int mt = 0; mt < 4; mt++) {
        const int r = wm * 64 + mt * 16 + qr;
        af[mt][0] = au[r * 36 + c];
        af[mt][1] = au[(r + 8) * 36 + c];
        af[mt][2] = au[r * 36 + c + 4];
        af[mt][3] = au[(r + 8) * 36 + c + 4];
      }
#pragma unroll
      for (int nt = 0; nt < 4; nt++) {
        const int n = wn * 32 + nt * 8 + qr;
        bf[nt][0] = bu[n * 36 + c];
        bf[nt][1] = bu[n * 36 + c + 4];
      }
#pragma unroll
      for (int mt = 0; mt < 4; mt++)
#pragma unroll
        for (int nt = 0; nt < 4; nt++) mma_bf16(acc[mt][nt], af[mt], bf[nt]);
    }
    __syncthreads();
  }

  const float C_OUT = 0.91914503001805780f;  // 0.7/sqrt(0.58)
  const float C_X   = 0.39391929857916763f;  // 0.3/sqrt(0.58)
#pragma unroll
  for (int mt = 0; mt < 4; mt++)
#pragma unroll
    for (int nt = 0; nt < 4; nt++) {
      const int r = m0 + wm * 64 + mt * 16 + qr;
      const int cb = n0 + wn * 32 + nt * 8 + qc * 2;
      const float* a4 = acc[mt][nt];
      if (FUSE) {
        float2 r0 = *(const float2*)&resid[(size_t)r * NCOLS + cb];
        float2 r1 = *(const float2*)&resid[(size_t)(r + 8) * NCOLS + cb];
        *(float2*)&C[(size_t)r * NCOLS + cb] =
            make_float2(a4[0] * C_OUT + r0.x * C_X, a4[1] * C_OUT + r0.y * C_X);
        *(float2*)&C[(size_t)(r + 8) * NCOLS + cb] =
            make_float2(a4[2] * C_OUT + r1.x * C_X, a4[3] * C_OUT + r1.y * C_X);
      } else {
        *(float2*)&C[(size_t)r * NCOLS + cb] = make_float2(a4[0], a4[1]);
        *(float2*)&C[(size_t)(r + 8) * NCOLS + cb] = make_float2(a4[2], a4[3]);
      }
    }
}

// ---------------- bf16 tensor-core flash attention, pixel-norm fused ----------------
// CTA: 128 q-rows of one (b,h); 8 warps, warp w owns q-rows [w*16, w*16+16).
// KV tile 64. Smem (uint = half2 units): Ks2 [64 kv][32 dpair +4 pad],
// Vt2 [64 d][32 kvpair +4 pad] with XOR swizzle col ^= ((d>>3)<<2) for the
// transpose store (32 distinct banks both directions). Q held as A-frags in
// registers; P stays entirely in registers (S C-frag == PV A-frag for bf16 k16).
static constexpr int kAttnSmemBytes = 4608 * 4;  // 18432

__global__ __launch_bounds__(256, 2) void attn_kernel(const float* __restrict__ memkv) {
  extern __shared__ uint32_t su[];  // 4608 uints
  uint32_t* Ks2 = su;          // [64][36]
  uint32_t* Vt2 = su + 2304;   // [64][36]

  const float* __restrict__ qkv = g_qkv;
  const int t = threadIdx.x;
  const int lane = t & 31, warp = t >> 5;
  const int qr = lane >> 2, qc = lane & 3;
  const int qt = blockIdx.x;
  const int b = blockIdx.y >> 4, h = blockIdx.y & 15;

  // ---- stage + pixel-norm Q (128 rows x 32 half2, stride 36, spans Ks2+Vt2) ----
  {
    const int rr = t >> 1, half = t & 1;  // 2 threads per row, 32 cols each
    const float* qp = qkv + (size_t)(b * kN + qt * 128 + rr) * kQkvN + h * 64 + half * 32;
    float4 q4[8];
    float ss = 0.f;
#pragma unroll
    for (int u = 0; u < 8; u++) {
      q4[u] = *(const float4*)(qp + u * 4);
      ss += q4[u].x * q4[u].x + q4[u].y * q4[u].y + q4[u].z * q4[u].z + q4[u].w * q4[u].w;
    }
    ss += __shfl_xor_sync(0xffffffffu, ss, 1);
    const float sc = 1.0f / fmaxf(sqrtf(ss), 1e-4f);
    uint32_t* dst = su + rr * 36 + half * 16;
#pragma unroll
    for (int u = 0; u < 4; u++) {
      uint4 pk;
      pk.x = bfpack(q4[u * 2].x * sc, q4[u * 2].y * sc);
      pk.y = bfpack(q4[u * 2].z * sc, q4[u * 2].w * sc);
      pk.z = bfpack(q4[u * 2 + 1].x * sc, q4[u * 2 + 1].y * sc);
      pk.w = bfpack(q4[u * 2 + 1].z * sc, q4[u * 2 + 1].w * sc);
      *(uint4*)(dst + u * 4) = pk;
    }
  }
  __syncthreads();

  // ---- Q A-fragments -> registers (held for entire kernel) ----
  uint32_t qf[4][4];
  {
    const int m = warp * 16 + qr;
#pragma unroll
    for (int kc = 0; kc < 4; kc++) {
      qf[kc][0] = su[m * 36 + kc * 8 + qc];
      qf[kc][1] = su[(m + 8) * 36 + kc * 8 + qc];
      qf[kc][2] = su[m * 36 + kc * 8 + qc + 4];
      qf[kc][3] = su[(m + 8) * 36 + kc * 8 + qc + 4];
    }
  }

  float oacc[8][4];
#pragma unroll
  for (int nt = 0; nt < 8; nt++)
#pragma unroll
    for (int r = 0; r < 4; r++) oacc[nt][r] = 0.f;
  float mr0 = -INFINITY, mr1 = -INFINITY, lr0 = 0.f, lr1 = 0.f;

  const int pr = t >> 3, lq8 = t & 7;  // kv loader: pair row 0..31, 8 d-threads/row

  for (int j0 = 0; j0 < kKV; j0 += 64) {
    const int L = (kKV - j0 < 64) ? (kKV - j0) : 64;

    // load two adjacent kv rows (2pr, 2pr+1), 8 d values each at d0 = lq8*8
    float ka[8], kb8[8], va[8], vb[8];
    float sska = 0.f, sskb = 0.f, ssva = 0.f, ssvb = 0.f;
    auto loadrow = [&](int j, float* kk, float* vv, float& ssk, float& ssv) {
      if (j < kKV) {
        const float *kp, *vp;
        if (j < 4) {
          kp = memkv + (size_t)(h * 4 + j) * 64 + lq8 * 8;
          vp = memkv + (size_t)((kHeads + h) * 4 + j) * 64 + lq8 * 8;
        } else {
          const size_t base = (size_t)(b * kN + (j - 4)) * kQkvN + h * 64 + lq8 * 8;
          kp = qkv + base + 1024;
          vp = qkv + base + 2048;
        }
#pragma unroll
        for (int u = 0; u < 2; u++) {
          float4 k4 = *(const float4*)(kp + u * 4);
          float4 v4 = *(const float4*)(vp + u * 4);
          kk[u * 4 + 0] = k4.x; kk[u * 4 + 1] = k4.y; kk[u * 4 + 2] = k4.z; kk[u * 4 + 3] = k4.w;
          vv[u * 4 + 0] = v4.x; vv[u * 4 + 1] = v4.y; vv[u * 4 + 2] = v4.z; vv[u * 4 + 3] = v4.w;
          ssk += k4.x * k4.x + k4.y * k4.y + k4.z * k4.z + k4.w * k4.w;
          ssv += v4.x * v4.x + v4.y * v4.y + v4.z * v4.z + v4.w * v4.w;
        }
      } else {
#pragma unroll
        for (int u = 0; u < 8; u++) { kk[u] = 0.f; vv[u] = 0.f; }
      }
    };
    loadrow(j0 + 2 * pr,     ka,  va, sska, ssva);
    loadrow(j0 + 2 * pr + 1, kb8, vb, sskb, ssvb);
#pragma unroll
    for (int off = 1; off <= 4; off <<= 1) {  // reduce over the 8 d-threads
      sska += __shfl_xor_sync(0xffffffffu, sska, off);
      sskb += __shfl_xor_sync(0xffffffffu, sskb, off);
      ssva += __shfl_xor_sync(0xffffffffu, ssva, off);
      ssvb += __shfl_xor_sync(0xffffffffu, ssvb, off);
    }
    const float ska = 8.0f / fmaxf(sqrtf(sska), 1e-4f);
    const float skb = 8.0f / fmaxf(sqrtf(sskb), 1e-4f);
    const float sva = 8.0f / fmaxf(sqrtf(ssva), 1e-4f);
    const float svb = 8.0f / fmaxf(sqrtf(ssvb), 1e-4f);

    __syncthreads();  // previous tile (or Q stage/frag reads) fully consumed
    {
      // K: row-major [kv][dpair]
      uint4 p0, p1;
      p0.x = bfpack(ka[0] * ska, ka[1] * ska);
      p0.y = bfpack(ka[2] * ska, ka[3] * ska);
      p0.z = bfpack(ka[4] * ska, ka[5] * ska);
      p0.w = bfpack(ka[6] * ska, ka[7] * ska);
      p1.x = bfpack(kb8[0] * skb, kb8[1] * skb);
      p1.y = bfpack(kb8[2] * skb, kb8[3] * skb);
      p1.z = bfpack(kb8[4] * skb, kb8[5] * skb);
      p1.w = bfpack(kb8[6] * skb, kb8[7] * skb);
      *(uint4*)(Ks2 + (2 * pr) * 36 + lq8 * 4) = p0;
      *(uint4*)(Ks2 + (2 * pr + 1) * 36 + lq8 * 4) = p1;
      // V: transposed [d][kvpair], swizzled col = pr ^ (lq8<<2)
      const int col = pr ^ (lq8 << 2);
#pragma unroll
      for (int i = 0; i < 8; i++)
        Vt2[(lq8 * 8 + i) * 36 + col] = bfpack(va[i] * sva, vb[i] * svb);
    }
    __syncthreads();

    // ---- S = Qn @ Kn^T (per warp: m16 x n64 x k64; 32 HMMA) ----
    float sf[8][4];
#pragma unroll
    for (int nt = 0; nt < 8; nt++)
#pragma unroll
      for (int r = 0; r < 4; r++) sf[nt][r] = 0.f;
#pragma unroll
    for (int nt = 0; nt < 8; nt++) {
      const int n = nt * 8 + qr;
#pragma unroll
      for (int kc = 0; kc < 4; kc++) {
        uint32_t bfr[2];
        bfr[0] = Ks2[n * 36 + kc * 8 + qc];
        bfr[1] = Ks2[n * 36 + kc * 8 + qc + 4];
        mma_bf16(sf[nt], qf[kc], bfr);
      }
    }
    if (L < 64) {
#pragma unroll
      for (int nt = 0; nt < 8; nt++) {
        const int c0 = nt * 8 + 2 * qc;
        if (c0 >= L)     { sf[nt][0] = -1e30f; sf[nt][2] = -1e30f; }
        if (c0 + 1 >= L) { sf[nt][1] = -1e30f; sf[nt][3] = -1e30f; }
      }
    }

    // ---- online softmax on c-fragments (thread owns rows qr, qr+8) ----
    {
      float mx0 = -INFINITY, mx1 = -INFINITY;
#pragma unroll
      for (int nt = 0; nt < 8; nt++) {
        mx0 = fmaxf(mx0, fmaxf(sf[nt][0], sf[nt][1]));
        mx1 = fmaxf(mx1, fmaxf(sf[nt][2], sf[nt][3]));
      }
      mx0 = fmaxf(mx0, __shfl_xor_sync(0xffffffffu, mx0, 1));
      mx0 = fmaxf(mx0, __shfl_xor_sync(0xffffffffu, mx0, 2));
      mx1 = fmaxf(mx1, __shfl_xor_sync(0xffffffffu, mx1, 1));
      mx1 = fmaxf(mx1, __shfl_xor_sync(0xffffffffu, mx1, 2));
      const float mn0 = fmaxf(mr0, mx0), mn1 = fmaxf(mr1, mx1);
      const float a0 = __expf(mr0 - mn0), a1 = __expf(mr1 - mn1);
      mr0 = mn0; mr1 = mn1;
      float rs0 = 0.f, rs1 = 0.f;
#pragma unroll
      for (int nt = 0; nt < 8; nt++) {
        sf[nt][0] = __expf(sf[nt][0] - mn0); rs0 += sf[nt][0];
        sf[nt][1] = __expf(sf[nt][1] - mn0); rs0 += sf[nt][1];
        sf[nt][2] = __expf(sf[nt][2] - mn1); rs1 += sf[nt][2];
        sf[nt][3] = __expf(sf[nt][3] - mn1); rs1 += sf[nt][3];
      }
      rs0 += __shfl_xor_sync(0xffffffffu, rs0, 1);
      rs0 += __shfl_xor_sync(0xffffffffu, rs0, 2);
      rs1 += __shfl_xor_sync(0xffffffffu, rs1, 1);
      rs1 += __shfl_xor_sync(0xffffffffu, rs1, 2);
      lr0 = lr0 * a0 + rs0;
      lr1 = lr1 * a1 + rs1;
#pragma unroll
      for (int nt = 0; nt < 8; nt++) {
        oacc[nt][0] *= a0; oacc[nt][1] *= a0;
        oacc[nt][2] *= a1; oacc[nt][3] *= a1;
      }
    }

    // ---- O += P @ Vn : P stays in registers (S C-frag == PV A-frag) ----
#pragma unroll
    for (int kt = 0; kt < 4; kt++) {
      uint32_t pa[4];
      pa[0] = bfpack(sf[2 * kt][0],     sf[2 * kt][1]);
      pa[1] = bfpack(sf[2 * kt][2],     sf[2 * kt][3]);
      pa[2] = bfpack(sf[2 * kt + 1][0], sf[2 * kt + 1][1]);
      pa[3] = bfpack(sf[2 * kt + 1][2], sf[2 * kt + 1][3]);
#pragma unroll
      for (int nt = 0; nt < 8; nt++) {
        const int n = nt * 8 + qr;
        const int swz = nt << 2;
        uint32_t bfr[2];
        bfr[0] = Vt2[n * 36 + ((kt * 8 + qc) ^ swz)];
        bfr[1] = Vt2[n * 36 + ((kt * 8 + qc + 4) ^ swz)];
        mma_bf16(oacc[nt], pa, bfr);
      }
    }
  }

  // ---- epilogue: normalize, write g_attn16 [b,n,h*d] as bf16 ----
  {
    const float i0 = 1.0f / lr0, i1 = 1.0f / lr1;
    const size_t r0 = (size_t)(b * kN + qt * 128 + warp * 16 + qr);
    uint32_t* out = (uint32_t*)g_attn16;
#pragma unroll
    for (int nt = 0; nt < 8; nt++) {
      const int col = h * 64 + nt * 8 + 2 * qc;
      out[(r0 * kDim + col) >> 1] = bfpack(oacc[nt][0] * i0, oacc[nt][1] * i0);
      out[((r0 + 8) * kDim + col) >> 1] = bfpack(oacc[nt][2] * i1, oacc[nt][3] * i1);
    }
  }
}

// ---------------- launch ----------------
extern "C" void kernel_launch(void* const* d_in, const int* in_sizes, int n_in,
                              void* d_out, int out_size) {
  const float *x = nullptr, *wq = nullptr, *wo = nullptr, *mkv = nullptr;
  for (int i = 0; i < n_in; i++) {
    switch (in_sizes[i]) {
      case kRows * kDim:        x   = (const float*)d_in[i]; break;  // 4194304
      case kQkvN * kDim:        wq  = (const float*)d_in[i]; break;  // 3145728
      case kDim * kDim:         wo  = (const float*)d_in[i]; break;  // 1048576
      case 2 * kHeads * 4 * kD: mkv = (const float*)d_in[i]; break;  // 8192
    }
  }
  if (!x || !wq || !wo || !mkv) return;

  static bool attr_set = false;
  if (!attr_set) {
    cudaFuncSetAttribute(gemm_bf16_kernel<kQkvN, false>,
                         cudaFuncAttributeMaxDynamicSharedMemorySize, 4 * 4608 * 4);
    cudaFuncSetAttribute(gemm_bf16_kernel<kDim, true>,
                         cudaFuncAttributeMaxDynamicSharedMemorySize, 4 * 4608 * 4);
    cudaFuncSetAttribute(attn_kernel,
                         cudaFuncAttributeMaxDynamicSharedMemorySize, kAttnSmemBytes);
    attr_set = true;
  }

  conv_x_kernel<<<kRows * kDim / 1024, 256>>>(x);
  norm_rows_kernel<<<kQkvN, 256>>>(wq, 0);
  norm_rows_kernel<<<kDim, 256>>>(wo, 1);

  // qkv = x16 @ wn_qkv16^T  (fp32 accumulate/output)
  {
    __nv_bfloat16 *xin, *wnq;
    float* qkvp;
    cudaGetSymbolAddress((void**)&xin, g_x16);
    cudaGetSymbolAddress((void**)&wnq, g_wn_qkv16);
    cudaGetSymbolAddress((void**)&qkvp, g_qkv);
    gemm_bf16_kernel<kQkvN, false><<<dim3(kQkvN / 128, kRows / 128), 256, 4 * 4608 * 4>>>(
        xin, wnq, qkvp, nullptr);
  }

  attn_kernel<<<dim3(kN / 128, kB * kHeads), 256, kAttnSmemBytes>>>(mkv);

  // out = (attn16 @ wn_out16^T) * c_out + x * c_x
  {
    __nv_bfloat16 *attn_in, *wno;
    cudaGetSymbolAddress((void**)&attn_in, g_attn16);
    cudaGetSymbolAddress((void**)&wno, g_wn_out16);
    gemm_bf16_kernel<kDim, true><<<dim3(kDim / 128, kRows / 128), 256, 4 * 4608 * 4>>>(
        attn_in, wno, (float*)d_out, x);
  }
}

// round 15
// speedup vs baseline: 4.5468x; 1.0127x over previous
#include <cuda_runtime.h>
#include <cuda_bf16.h>
#include <math.h>
#include <stdint.h>

static constexpr int kHeads = 16;
static constexpr int kD     = 64;
static constexpr int kB     = 2;
static constexpr int kN     = 2048;
static constexpr int kDim   = 1024;
static constexpr int kRows  = kB * kN;          // 4096
static constexpr int kQkvN  = 3 * kHeads * kD;  // 3072
static constexpr int kKV    = kN + 4;           // 2052

// ---------------- scratch (device globals; no allocation) ----------------
__device__ __nv_bfloat16 g_x16[(size_t)kRows * kDim];
__device__ __nv_bfloat16 g_wn_qkv16[(size_t)kQkvN * kDim];
__device__ __nv_bfloat16 g_wn_out16[(size_t)kDim * kDim];
__device__ __nv_bfloat16 g_attn16[(size_t)kRows * kDim];
__device__ float g_qkv[(size_t)kRows * kQkvN];

__device__ __forceinline__ uint32_t bfpack(float lo, float hi) {
  uint32_t r;
  asm("cvt.rn.bf16x2.f32 %0, %1, %2;" : "=r"(r) : "f"(hi), "f"(lo));
  return r;
}

__device__ __forceinline__ void cp16(uint32_t* s, const void* g) {
  uint32_t sa = (uint32_t)__cvta_generic_to_shared(s);
  asm volatile("cp.async.cg.shared.global [%0], [%1], 16;\n" :: "r"(sa), "l"(g));
}

__device__ __forceinline__ void mma_bf16(float* d, const uint32_t* a, const uint32_t* b) {
  asm volatile(
      "mma.sync.aligned.m16n8k16.row.col.f32.bf16.bf16.f32 "
      "{%0,%1,%2,%3}, {%4,%5,%6,%7}, {%8,%9}, {%0,%1,%2,%3};\n"
      : "+f"(d[0]), "+f"(d[1]), "+f"(d[2]), "+f"(d[3])
      : "r"(a[0]), "r"(a[1]), "r"(a[2]), "r"(a[3]), "r"(b[0]), "r"(b[1]));
}

__device__ __forceinline__ void ldsm4(uint32_t* r, uint32_t addr) {
  asm volatile("ldmatrix.sync.aligned.m8n8.x4.shared.b16 {%0,%1,%2,%3}, [%4];"
               : "=r"(r[0]), "=r"(r[1]), "=r"(r[2]), "=r"(r[3]) : "r"(addr));
}

// ---------------- convert x to bf16 ----------------
__global__ __launch_bounds__(256) void conv_x_kernel(const float* __restrict__ x) {
  const int i = blockIdx.x * 256 + threadIdx.x;  // one float4 each
  float4 v = ((const float4*)x)[i];
  ((uint2*)g_x16)[i] = make_uint2(bfpack(v.x, v.y), bfpack(v.z, v.w));
}

// ---------------- weight row l2-norm -> bf16 ----------------
__global__ __launch_bounds__(256) void norm_rows_kernel(const float* __restrict__ w, int which) {
  __nv_bfloat16* wn = which ? g_wn_out16 : g_wn_qkv16;
  const int row = blockIdx.x;
  const int t = threadIdx.x;  // 256 threads, 1024 cols -> 1 float4 each
  float4 v = ((const float4*)(w + (size_t)row * kDim))[t];
  float ss = v.x * v.x + v.y * v.y + v.z * v.z + v.w * v.w;
#pragma unroll
  for (int off = 16; off; off >>= 1) ss += __shfl_xor_sync(0xffffffffu, ss, off);
  __shared__ float red[8];
  if ((t & 31) == 0) red[t >> 5] = ss;
  __syncthreads();
  float tot = red[0] + red[1] + red[2] + red[3] + red[4] + red[5] + red[6] + red[7];
  float sc = 1.0f / (fmaxf(sqrtf(tot), 1e-4f) * 32.0f);  // 32 = sqrt(1024)
  ((uint2*)(wn + (size_t)row * kDim))[t] =
      make_uint2(bfpack(v.x * sc, v.y * sc), bfpack(v.z * sc, v.w * sc));
}

// ---------------- bf16 tensor-core GEMM: C[m,n] = sum_k A[m,k]*B[n,k] ----------------
// 128x128 CTA tile, BK=64 halves, 2-stage cp.async, 8 warps (2x4), warp tile
// 64x32 = 4x4 m16n8k16 frags. Fragments loaded via ldmatrix.x4 (stride 36 uints:
// 8-row phases cover all 32 banks -> conflict-free).
template <int NCOLS, bool FUSE>
__global__ __launch_bounds__(256, 2) void gemm_bf16_kernel(const __nv_bfloat16* __restrict__ A,
                                                           const __nv_bfloat16* __restrict__ Bw,
                                                           float* __restrict__ C,
                                                           const float* __restrict__ resid) {
  extern __shared__ uint32_t sg[];
  uint32_t* AsBuf[2] = {sg, sg + 4608};
  uint32_t* BsBuf[2] = {sg + 9216, sg + 13824};

  const int t = threadIdx.x, lane = t & 31, warp = t >> 5;
  const int wm = warp >> 2, wn = warp & 3;
  const int m0 = blockIdx.y * 128, n0 = blockIdx.x * 128;
  const int srow = t >> 1, sc2 = (t & 1) * 16;  // half2 col offset
  const __nv_bfloat16* gA = A + (size_t)(m0 + srow) * kDim + sc2 * 2;
  const __nv_bfloat16* gB = Bw + (size_t)(n0 + srow) * kDim + sc2 * 2;

  auto prefetch = [&](int s, int k0) {  // k0 in halves
    uint32_t* da = AsBuf[s] + srow * 36 + sc2;
    uint32_t* db = BsBuf[s] + srow * 36 + sc2;
#pragma unroll
    for (int u = 0; u < 4; u++) {
      cp16(da + u * 4, gA + k0 + u * 8);
      cp16(db + u * 4, gB + k0 + u * 8);
    }
  };

  float acc[4][4][4];
#pragma unroll
  for (int mt = 0; mt < 4; mt++)
#pragma unroll
    for (int nt = 0; nt < 4; nt++)
#pragma unroll
      for (int r = 0; r < 4; r++) acc[mt][nt][r] = 0.f;

  prefetch(0, 0);
  asm volatile("cp.async.commit_group;\n");

  const int qr = lane >> 2, qc = lane & 3;
  // ldmatrix lane offsets (uint units, relative to tile base):
  // A x4 -> {[r][c],[r+8][c],[r][c+4],[r+8][c+4]}
  const int a_off = (wm * 64 + (lane & 7) + ((lane >> 3) & 1) * 8) * 36 + (lane >> 4) * 4;
  // B x4 (covers nt pair) -> {bf[lo][0], bf[lo][1], bf[hi][0], bf[hi][1]}
  const int b_off = (wn * 32 + (lane & 7) + ((lane >> 4) & 1) * 8) * 36 + ((lane >> 3) & 1) * 4;

#pragma unroll 1
  for (int kb = 0; kb < 16; kb++) {  // 16 x 64 halves = 1024
    const int cur = kb & 1;
    if (kb < 15) {
      prefetch(cur ^ 1, (kb + 1) * 64);
      asm volatile("cp.async.commit_group;\n");
      asm volatile("cp.async.wait_group 1;\n");
    } else {
      asm volatile("cp.async.wait_group 0;\n");
    }
    __syncthreads();

    const uint32_t baseA = (uint32_t)__cvta_generic_to_shared(AsBuf[cur]);
    const uint32_t baseB = (uint32_t)__cvta_generic_to_shared(BsBuf[cur]);
#pragma unroll
    for (int kt = 0; kt < 4; kt++) {  // 4 x k16
      uint32_t af[4][4], bq[2][4];
      ldsm4(bq[0], baseB + 4u * (b_off + kt * 8));
      ldsm4(bq[1], baseB + 4u * (b_off + 16 * 36 + kt * 8));
#pragma unroll
      for (int mt = 0; mt < 4; mt++)
        ldsm4(af[mt], baseA + 4u * (a_off + mt * 16 * 36 + kt * 8));
#pragma unroll
      for (int mt = 0; mt < 4; mt++)
#pragma unroll
        for (int nt = 0; nt < 4; nt++)
          mma_bf16(acc[mt][nt], af[mt], &bq[nt >> 1][(nt & 1) * 2]);
    }
    __syncthreads();
  }

  const float C_OUT = 0.91914503001805780f;  // 0.7/sqrt(0.58)
  const float C_X   = 0.39391929857916763f;  // 0.3/sqrt(0.58)
#pragma unroll
  for (int mt = 0; mt < 4; mt++)
#pragma unroll
    for (int nt = 0; nt < 4; nt++) {
      const int r = m0 + wm * 64 + mt * 16 + qr;
      const int cb = n0 + wn * 32 + nt * 8 + qc * 2;
      const float* a4 = acc[mt][nt];
      if (FUSE) {
        float2 r0 = *(const float2*)&resid[(size_t)r * NCOLS + cb];
        float2 r1 = *(const float2*)&resid[(size_t)(r + 8) * NCOLS + cb];
        *(float2*)&C[(size_t)r * NCOLS + cb] =
            make_float2(a4[0] * C_OUT + r0.x * C_X, a4[1] * C_OUT + r0.y * C_X);
        *(float2*)&C[(size_t)(r + 8) * NCOLS + cb] =
            make_float2(a4[2] * C_OUT + r1.x * C_X, a4[3] * C_OUT + r1.y * C_X);
      } else {
        *(float2*)&C[(size_t)r * NCOLS + cb] = make_float2(a4[0], a4[1]);
        *(float2*)&C[(size_t)(r + 8) * NCOLS + cb] = make_float2(a4[2], a4[3]);
      }
    }
}

// ---------------- bf16 tensor-core flash attention, pixel-norm fused ----------------
// CTA: 128 q-rows of one (b,h); 8 warps. KV tile 64, software-prefetched:
// pack regs->smem frees the registers, next tile's LDGs issue immediately and
// their latency hides behind S-mma/softmax/PV of the current tile.
static constexpr int kAttnSmemBytes = 4608 * 4;  // 18432

__global__ __launch_bounds__(256, 2) void attn_kernel(const float* __restrict__ memkv) {
  extern __shared__ uint32_t su[];  // 4608 uints
  uint32_t* Ks2 = su;          // [64][36]
  uint32_t* Vt2 = su + 2304;   // [64][36]

  const float* __restrict__ qkv = g_qkv;
  const int t = threadIdx.x;
  const int lane = t & 31, warp = t >> 5;
  const int qr = lane >> 2, qc = lane & 3;
  const int qt = blockIdx.x;
  const int b = blockIdx.y >> 4, h = blockIdx.y & 15;

  // ---- stage + pixel-norm Q (128 rows x 32 half2, stride 36, spans Ks2+Vt2) ----
  {
    const int rr = t >> 1, half = t & 1;  // 2 threads per row, 32 cols each
    const float* qp = qkv + (size_t)(b * kN + qt * 128 + rr) * kQkvN + h * 64 + half * 32;
    float4 q4[8];
    float ss = 0.f;
#pragma unroll
    for (int u = 0; u < 8; u++) {
      q4[u] = *(const float4*)(qp + u * 4);
      ss += q4[u].x * q4[u].x + q4[u].y * q4[u].y + q4[u].z * q4[u].z + q4[u].w * q4[u].w;
    }
    ss += __shfl_xor_sync(0xffffffffu, ss, 1);
    const float sc = 1.0f / fmaxf(sqrtf(ss), 1e-4f);
    uint32_t* dst = su + rr * 36 + half * 16;
#pragma unroll
    for (int u = 0; u < 4; u++) {
      uint4 pk;
      pk.x = bfpack(q4[u * 2].x * sc, q4[u * 2].y * sc);
      pk.y = bfpack(q4[u * 2].z * sc, q4[u * 2].w * sc);
      pk.z = bfpack(q4[u * 2 + 1].x * sc, q4[u * 2 + 1].y * sc);
      pk.w = bfpack(q4[u * 2 + 1].z * sc, q4[u * 2 + 1].w * sc);
      *(uint4*)(dst + u * 4) = pk;
    }
  }
  __syncthreads();

  // ---- Q A-fragments -> registers (held for entire kernel) ----
  uint32_t qf[4][4];
  {
    const int m = warp * 16 + qr;
#pragma unroll
    for (int kc = 0; kc < 4; kc++) {
      qf[kc][0] = su[m * 36 + kc * 8 + qc];
      qf[kc][1] = su[(m + 8) * 36 + kc * 8 + qc];
      qf[kc][2] = su[m * 36 + kc * 8 + qc + 4];
      qf[kc][3] = su[(m + 8) * 36 + kc * 8 + qc + 4];
    }
  }

  float oacc[8][4];
#pragma unroll
  for (int nt = 0; nt < 8; nt++)
#pragma unroll
    for (int r = 0; r < 4; r++) oacc[nt][r] = 0.f;
  float mr0 = -INFINITY, mr1 = -INFINITY, lr0 = 0.f, lr1 = 0.f;

  const int pr = t >> 3, lq8 = t & 7;  // kv loader: pair row 0..31, 8 d-threads/row

  // KV register tile (single buffer, refilled right after the smem pack)
  float ka[8], kb8[8], va[8], vb[8];
  auto loadrow = [&](int j, float* kk, float* vv) {
    if (j < kKV) {
      const float *kp, *vp;
      if (j < 4) {
        kp = memkv + (size_t)(h * 4 + j) * 64 + lq8 * 8;
        vp = memkv + (size_t)((kHeads + h) * 4 + j) * 64 + lq8 * 8;
      } else {
        const size_t base = (size_t)(b * kN + (j - 4)) * kQkvN + h * 64 + lq8 * 8;
        kp = qkv + base + 1024;
        vp = qkv + base + 2048;
      }
#pragma unroll
      for (int u = 0; u < 2; u++) {
        float4 k4 = *(const float4*)(kp + u * 4);
        float4 v4 = *(const float4*)(vp + u * 4);
        kk[u * 4 + 0] = k4.x; kk[u * 4 + 1] = k4.y; kk[u * 4 + 2] = k4.z; kk[u * 4 + 3] = k4.w;
        vv[u * 4 + 0] = v4.x; vv[u * 4 + 1] = v4.y; vv[u * 4 + 2] = v4.z; vv[u * 4 + 3] = v4.w;
      }
    } else {
#pragma unroll
      for (int u = 0; u < 8; u++) { kk[u] = 0.f; vv[u] = 0.f; }
    }
  };

  loadrow(2 * pr, ka, va);          // prologue: tile 0
  loadrow(2 * pr + 1, kb8, vb);

  for (int j0 = 0; j0 < kKV; j0 += 64) {
    const int L = (kKV - j0 < 64) ? (kKV - j0) : 64;

    // ---- pixel-norm scales from regs (loads completed during prev compute) ----
    float sska = 0.f, sskb = 0.f, ssva = 0.f, ssvb = 0.f;
#pragma unroll
    for (int u = 0; u < 8; u++) {
      sska += ka[u] * ka[u]; sskb += kb8[u] * kb8[u];
      ssva += va[u] * va[u]; ssvb += vb[u] * vb[u];
    }
#pragma unroll
    for (int off = 1; off <= 4; off <<= 1) {  // reduce over the 8 d-threads
      sska += __shfl_xor_sync(0xffffffffu, sska, off);
      sskb += __shfl_xor_sync(0xffffffffu, sskb, off);
      ssva += __shfl_xor_sync(0xffffffffu, ssva, off);
      ssvb += __shfl_xor_sync(0xffffffffu, ssvb, off);
    }
    const float ska = 8.0f / fmaxf(sqrtf(sska), 1e-4f);
    const float skb = 8.0f / fmaxf(sqrtf(sskb), 1e-4f);
    const float sva = 8.0f / fmaxf(sqrtf(ssva), 1e-4f);
    const float svb = 8.0f / fmaxf(sqrtf(ssvb), 1e-4f);

    __syncthreads();  // previous tile (or Q stage/frag reads) fully consumed
    {
      // K: row-major [kv][dpair]
      uint4 p0, p1;
      p0.x = bfpack(ka[0] * ska, ka[1] * ska);
      p0.y = bfpack(ka[2] * ska, ka[3] * ska);
      p0.z = bfpack(ka[4] * ska, ka[5] * ska);
      p0.w = bfpack(ka[6] * ska, ka[7] * ska);
      p1.x = bfpack(kb8[0] * skb, kb8[1] * skb);
      p1.y = bfpack(kb8[2] * skb, kb8[3] * skb);
      p1.z = bfpack(kb8[4] * skb, kb8[5] * skb);
      p1.w = bfpack(kb8[6] * skb, kb8[7] * skb);
      *(uint4*)(Ks2 + (2 * pr) * 36 + lq8 * 4) = p0;
      *(uint4*)(Ks2 + (2 * pr + 1) * 36 + lq8 * 4) = p1;
      // V: transposed [d][kvpair], swizzled col = pr ^ (lq8<<2)
      const int col = pr ^ (lq8 << 2);
#pragma unroll
      for (int i = 0; i < 8; i++)
        Vt2[(lq8 * 8 + i) * 36 + col] = bfpack(va[i] * sva, vb[i] * svb);
    }
    __syncthreads();

    // ---- prefetch next tile into the (now dead) KV registers ----
    if (j0 + 64 < kKV) {
      loadrow(j0 + 64 + 2 * pr, ka, va);
      loadrow(j0 + 64 + 2 * pr + 1, kb8, vb);
    }

    // ---- S = Qn @ Kn^T (per warp: m16 x n64 x k64; 32 HMMA) ----
    float sf[8][4];
#pragma unroll
    for (int nt = 0; nt < 8; nt++)
#pragma unroll
      for (int r = 0; r < 4; r++) sf[nt][r] = 0.f;
#pragma unroll
    for (int nt = 0; nt < 8; nt++) {
      const int n = nt * 8 + qr;
#pragma unroll
      for (int kc = 0; kc < 4; kc++) {
        uint32_t bfr[2];
        bfr[0] = Ks2[n * 36 + kc * 8 + qc];
        bfr[1] = Ks2[n * 36 + kc * 8 + qc + 4];
        mma_bf16(sf[nt], qf[kc], bfr);
      }
    }
    if (L < 64) {
#pragma unroll
      for (int nt = 0; nt < 8; nt++) {
        const int c0 = nt * 8 + 2 * qc;
        if (c0 >= L)     { sf[nt][0] = -1e30f; sf[nt][2] = -1e30f; }
        if (c0 + 1 >= L) { sf[nt][1] = -1e30f; sf[nt][3] = -1e30f; }
      }
    }

    // ---- online softmax on c-fragments (thread owns rows qr, qr+8) ----
    {
      float mx0 = -INFINITY, mx1 = -INFINITY;
#pragma unroll
      for (int nt = 0; nt < 8; nt++) {
        mx0 = fmaxf(mx0, fmaxf(sf[nt][0], sf[nt][1]));
        mx1 = fmaxf(mx1, fmaxf(sf[nt][2], sf[nt][3]));
      }
      mx0 = fmaxf(mx0, __shfl_xor_sync(0xffffffffu, mx0, 1));
      mx0 = fmaxf(mx0, __shfl_xor_sync(0xffffffffu, mx0, 2));
      mx1 = fmaxf(mx1, __shfl_xor_sync(0xffffffffu, mx1, 1));
      mx1 = fmaxf(mx1, __shfl_xor_sync(0xffffffffu, mx1, 2));
      const float mn0 = fmaxf(mr0, mx0), mn1 = fmaxf(mr1, mx1);
      const float a0 = __expf(mr0 - mn0), a1 = __expf(mr1 - mn1);
      mr0 = mn0; mr1 = mn1;
      float rs0 = 0.f, rs1 = 0.f;
#pragma unroll
      for (int nt = 0; nt < 8; nt++) {
        sf[nt][0] = __expf(sf[nt][0] - mn0); rs0 += sf[nt][0];
        sf[nt][1] = __expf(sf[nt][1] - mn0); rs0 += sf[nt][1];
        sf[nt][2] = __expf(sf[nt][2] - mn1); rs1 += sf[nt][2];
        sf[nt][3] = __expf(sf[nt][3] - mn1); rs1 += sf[nt][3];
      }
      rs0 += __shfl_xor_sync(0xffffffffu, rs0, 1);
      rs0 += __shfl_xor_sync(0xffffffffu, rs0, 2);
      rs1 += __shfl_xor_sync(0xffffffffu, rs1, 1);
      rs1 += __shfl_xor_sync(0xffffffffu, rs1, 2);
      lr0 = lr0 * a0 + rs0;
      lr1 = lr1 * a1 + rs1;
#pragma unroll
      for (int nt = 0; nt < 8; nt++) {
        oacc[nt][0] *= a0; oacc[nt][1] *= a0;
        oacc[nt][2] *= a1; oacc[nt][3] *= a1;
      }
    }

    // ---- O += P @ Vn : P stays in registers (S C-frag == PV A-frag) ----
#pragma unroll
    for (int kt = 0; kt < 4; kt++) {
      uint32_t pa[4];
      pa[0] = bfpack(sf[2 * kt][0],     sf[2 * kt][1]);
      pa[1] = bfpack(sf[2 * kt][2],     sf[2 * kt][3]);
      pa[2] = bfpack(sf[2 * kt + 1][0], sf[2 * kt + 1][1]);
      pa[3] = bfpack(sf[2 * kt + 1][2], sf[2 * kt + 1][3]);
#pragma unroll
      for (int nt = 0; nt < 8; nt++) {
        const int n = nt * 8 + qr;
        const int swz = nt << 2;
        uint32_t bfr[2];
        bfr[0] = Vt2[n * 36 + ((kt * 8 + qc) ^ swz)];
        bfr[1] = Vt2[n * 36 + ((kt * 8 + qc + 4) ^ swz)];
        mma_bf16(oacc[nt], pa, bfr);
      }
    }
  }

  // ---- epilogue: normalize, write g_attn16 [b,n,h*d] as bf16 ----
  {
    const float i0 = 1.0f / lr0, i1 = 1.0f / lr1;
    const size_t r0 = (size_t)(b * kN + qt * 128 + warp * 16 + qr);
    uint32_t* out = (uint32_t*)g_attn16;
#pragma unroll
    for (int nt = 0; nt < 8; nt++) {
      const int col = h * 64 + nt * 8 + 2 * qc;
      out[(r0 * kDim + col) >> 1] = bfpack(oacc[nt][0] * i0, oacc[nt][1] * i0);
      out[((r0 + 8) * kDim + col) >> 1] = bfpack(oacc[nt][2] * i1, oacc[nt][3] * i1);
    }
  }
}

// ---------------- launch ----------------
extern "C" void kernel_launch(void* const* d_in, const int* in_sizes, int n_in,
                              void* d_out, int out_size) {
  const float *x = nullptr, *wq = nullptr, *wo = nullptr, *mkv = nullptr;
  for (int i = 0; i < n_in; i++) {
    switch (in_sizes[i]) {
      case kRows * kDim:        x   = (const float*)d_in[i]; break;  // 4194304
      case kQkvN * kDim:        wq  = (const float*)d_in[i]; break;  // 3145728
      case kDim * kDim:         wo  = (const float*)d_in[i]; break;  // 1048576
      case 2 * kHeads * 4 * kD: mkv = (const float*)d_in[i]; break;  // 8192
    }
  }
  if (!x || !wq || !wo || !mkv) return;

  static bool attr_set = false;
  if (!attr_set) {
    cudaFuncSetAttribute(gemm_bf16_kernel<kQkvN, false>,
                         cudaFuncAttributeMaxDynamicSharedMemorySize, 4 * 4608 * 4);
    cudaFuncSetAttribute(gemm_bf16_kernel<kDim, true>,
                         cudaFuncAttributeMaxDynamicSharedMemorySize, 4 * 4608 * 4);
    cudaFuncSetAttribute(attn_kernel,
                         cudaFuncAttributeMaxDynamicSharedMemorySize, kAttnSmemBytes);
    attr_set = true;
  }

  conv_x_kernel<<<kRows * kDim / 1024, 256>>>(x);
  norm_rows_kernel<<<kQkvN, 256>>>(wq, 0);
  norm_rows_kernel<<<kDim, 256>>>(wo, 1);

  // qkv = x16 @ wn_qkv16^T  (fp32 accumulate/output)
  {
    __nv_bfloat16 *xin, *wnq;
    float* qkvp;
    cudaGetSymbolAddress((void**)&xin, g_x16);
    cudaGetSymbolAddress((void**)&wnq, g_wn_qkv16);
    cudaGetSymbolAddress((void**)&qkvp, g_qkv);
    gemm_bf16_kernel<kQkvN, false><<<dim3(kQkvN / 128, kRows / 128), 256, 4 * 4608 * 4>>>(
        xin, wnq, qkvp, nullptr);
  }

  attn_kernel<<<dim3(kN / 128, kB * kHeads), 256, kAttnSmemBytes>>>(mkv);

  // out = (attn16 @ wn_out16^T) * c_out + x * c_x
  {
    __nv_bfloat16 *attn_in, *wno;
    cudaGetSymbolAddress((void**)&attn_in, g_attn16);
    cudaGetSymbolAddress((void**)&wno, g_wn_out16);
    gemm_bf16_kernel<kDim, true><<<dim3(kDim / 128, kRows / 128), 256, 4 * 4608 * 4>>>(
        attn_in, wno, (float*)d_out, x);
  }
}